// round 6
// baseline (speedup 1.0000x reference)
#include <cuda_runtime.h>
#include <cuda_bf16.h>
#include <cstdint>

#define DEVINL __device__ __forceinline__

// ---------------- problem constants ----------------
constexpr int Sc = 2048, Dc = 64, BHc = 32;
constexpr int NKT = Sc / 128;                 // 16 k-tiles
constexpr int QT_ROWS = 64;                   // q-rows per CTA
constexpr int NQT = Sc / QT_ROWS;             // 32 q-tiles
constexpr int QKD = BHc * Sc * Dc;            // 4194304
constexpr int MASKW = Sc * Sc / 32;           // 131072
constexpr long long OUT_ELEMS  = (long long)QKD;
constexpr long long ATTN_ELEMS = (long long)BHc * Sc * Sc;

// ---------------- static device scratch ----------------
__device__ __nv_bfloat16 g_Qhi[QKD], g_Qlo[QKD], g_Khi[QKD], g_Klo[QKD];
__device__ __nv_bfloat16 g_Vthi[QKD], g_Vtlo[QKD];   // transposed: [bh][d][s]
__device__ unsigned g_maskbits[MASKW];

// ---------------- smem layout (padded rows, conflict-free LDS) -------------
constexpr int KROW = 144;                    // 64 bf16 (128B) + 16B pad
constexpr int VROW = 272;                    // 128 bf16 (256B) + 16B pad
constexpr int OFF_KHI = 0;
constexpr int OFF_KLO = 128 * KROW;          // 18432
constexpr int OFF_VHI = 2 * 128 * KROW;      // 36864
constexpr int OFF_VLO = OFF_VHI + 64 * VROW;
constexpr int SMEM_BYTES = OFF_VLO + 64 * VROW;  // 71680  (x3 CTAs = 215KB)

// ---------------- mma helpers ----------------
DEVINL void mma16816(float c[4], const uint32_t a[4], uint32_t b0, uint32_t b1) {
    asm volatile(
        "mma.sync.aligned.m16n8k16.row.col.f32.bf16.bf16.f32 "
        "{%0,%1,%2,%3}, {%4,%5,%6,%7}, {%8,%9}, {%0,%1,%2,%3};"
        : "+f"(c[0]), "+f"(c[1]), "+f"(c[2]), "+f"(c[3])
        : "r"(a[0]), "r"(a[1]), "r"(a[2]), "r"(a[3]), "r"(b0), "r"(b1));
}
DEVINL uint32_t pk2(float x, float y) {
    __nv_bfloat162 t = __floats2bfloat162_rn(x, y);
    return *(uint32_t*)&t;   // x in low half
}

// ---------------- preprocessing ----------------
// q is pre-scaled by 1/8 (=1/sqrt(64)) so the hot loop does exp(c) directly.
__global__ void conv_qk_kernel(const float* __restrict__ q, const float* __restrict__ k) {
    int i = blockIdx.x * 256 + threadIdx.x;
    float qv = q[i] * 0.125f;
    __nv_bfloat16 qh = __float2bfloat16(qv);
    g_Qhi[i] = qh;
    g_Qlo[i] = __float2bfloat16(qv - __bfloat162float(qh));
    float kv = k[i];
    __nv_bfloat16 kh = __float2bfloat16(kv);
    g_Khi[i] = kh;
    g_Klo[i] = __float2bfloat16(kv - __bfloat162float(kh));
}

// tiled transpose v[bh,s,d] -> g_Vt[bh,d,s] hi/lo
__global__ void conv_v_kernel(const float* __restrict__ v) {
    __shared__ float tile[64][65];
    int bh = blockIdx.x >> 5;
    int s0 = (blockIdx.x & 31) * 64;
    int tid = threadIdx.x;
    for (int i = tid; i < 64 * 64; i += 256) {
        int sr = i >> 6, dc = i & 63;
        tile[sr][dc] = v[((long long)bh * Sc + s0 + sr) * Dc + dc];
    }
    __syncthreads();
    for (int i = tid; i < 64 * 64; i += 256) {
        int dr = i >> 6, sc = i & 63;
        float vv = tile[sc][dr];
        __nv_bfloat16 vh = __float2bfloat16(vv);
        long long gi = ((long long)bh * Dc + dr) * Sc + s0 + sc;
        g_Vthi[gi] = vh;
        g_Vtlo[gi] = __float2bfloat16(vv - __bfloat162float(vh));
    }
}

__global__ void pack_mask_kernel(const int* __restrict__ m) {
    int i = blockIdx.x * 256 + threadIdx.x;     // row = i>>6, word = i&63
    int row = i >> 6, w = i & 63;
    const int4* p = (const int4*)(m + (long long)row * Sc + w * 32);
    unsigned bits = 0;
    #pragma unroll
    for (int g = 0; g < 8; ++g) {
        int4 x = p[g];
        bits |= (unsigned)(x.x != 0) << (g * 4 + 0);
        bits |= (unsigned)(x.y != 0) << (g * 4 + 1);
        bits |= (unsigned)(x.z != 0) << (g * 4 + 2);
        bits |= (unsigned)(x.w != 0) << (g * 4 + 3);
    }
    g_maskbits[i] = bits;
}

// ---------------- tile loaders (gmem -> padded smem) ----------------
DEVINL void load_k_tiles(char* smem, int bh, int kt, int tid) {
    const uint4* kh = (const uint4*)g_Khi + ((long long)bh * Sc + kt * 128) * 8;
    const uint4* kl = (const uint4*)g_Klo + ((long long)bh * Sc + kt * 128) * 8;
    #pragma unroll
    for (int i = tid; i < 128 * 8; i += 128) {
        int r = i >> 3, w = i & 7;
        int off = r * KROW + w * 16;
        *(uint4*)(smem + OFF_KHI + off) = kh[i];
        *(uint4*)(smem + OFF_KLO + off) = kl[i];
    }
}
DEVINL void load_v_tiles(char* smem, int bh, int kt, int tid) {
    const uint4* vh = (const uint4*)g_Vthi;
    const uint4* vl = (const uint4*)g_Vtlo;
    #pragma unroll
    for (int i = tid; i < 64 * 16; i += 128) {
        int d = i >> 4, w = i & 15;
        int off = d * VROW + w * 16;
        long long gi = ((long long)bh * 64 + d) * 256 + kt * 16 + w;
        *(uint4*)(smem + OFF_VHI + off) = vh[gi];
        *(uint4*)(smem + OFF_VLO + off) = vl[gi];
    }
}

// ---------------- main fused kernel ----------------
// 128 threads (4 warps), 64 q-rows per CTA, 3 CTAs/SM target.
__global__ void __launch_bounds__(128, 3)
attn_main_kernel(float* __restrict__ out, float* __restrict__ attn) {
    extern __shared__ __align__(16) char smem[];
    const int qt = blockIdx.x;             // 0..31
    const int bh = blockIdx.y;             // 0..31
    const int tid = threadIdx.x;
    const int wid = tid >> 5, lane = tid & 31;
    const int gid = lane >> 2, tig = lane & 3;
    const int r0 = wid * 16 + gid;         // q-row (block-local), second row r0+8
    const long long qrow0 = (long long)qt * QT_ROWS + r0;

    // ---- stage Q tile into K region, pull A-fragments to registers ----
    {
        const uint4* qh = (const uint4*)g_Qhi + ((long long)bh * Sc + qt * QT_ROWS) * 8;
        const uint4* ql = (const uint4*)g_Qlo + ((long long)bh * Sc + qt * QT_ROWS) * 8;
        #pragma unroll
        for (int i = tid; i < QT_ROWS * 8; i += 128) {
            int r = i >> 3, w = i & 7;
            int off = r * KROW + w * 16;
            *(uint4*)(smem + OFF_KHI + off) = qh[i];
            *(uint4*)(smem + OFF_KLO + off) = ql[i];
        }
    }
    __syncthreads();
    uint32_t qfh[4][4], qfl[4][4];
    #pragma unroll
    for (int kk = 0; kk < 4; ++kk) {
        int base = r0 * KROW + (kk * 16 + 2 * tig) * 2;
        qfh[kk][0] = *(const uint32_t*)(smem + OFF_KHI + base);
        qfh[kk][1] = *(const uint32_t*)(smem + OFF_KHI + base + 8 * KROW);
        qfh[kk][2] = *(const uint32_t*)(smem + OFF_KHI + base + 16);
        qfh[kk][3] = *(const uint32_t*)(smem + OFF_KHI + base + 8 * KROW + 16);
        qfl[kk][0] = *(const uint32_t*)(smem + OFF_KLO + base);
        qfl[kk][1] = *(const uint32_t*)(smem + OFF_KLO + base + 8 * KROW);
        qfl[kk][2] = *(const uint32_t*)(smem + OFF_KLO + base + 16);
        qfl[kk][3] = *(const uint32_t*)(smem + OFF_KLO + base + 8 * KROW + 16);
    }
    __syncthreads();

    const unsigned* mrow0 = g_maskbits + (long long)qrow0 * 64;
    const unsigned* mrow1 = mrow0 + 8 * 64;

    // ================ phase 1: row sums ================
    float lsum0 = 0.f, lsum1 = 0.f;
    for (int kt = 0; kt < NKT; ++kt) {
        load_k_tiles(smem, bh, kt, tid);
        __syncthreads();
        unsigned mw0[4], mw1[4];
        #pragma unroll
        for (int qd = 0; qd < 4; ++qd) { mw0[qd] = mrow0[kt * 4 + qd]; mw1[qd] = mrow1[kt * 4 + qd]; }
        #pragma unroll
        for (int nb = 0; nb < 16; ++nb) {
            float c[4] = {0.f, 0.f, 0.f, 0.f};
            #pragma unroll
            for (int kk = 0; kk < 4; ++kk) {
                int kb = (nb * 8 + gid) * KROW + (kk * 16 + 2 * tig) * 2;
                uint32_t bh0 = *(const uint32_t*)(smem + OFF_KHI + kb);
                uint32_t bh1 = *(const uint32_t*)(smem + OFF_KHI + kb + 16);
                uint32_t bl0 = *(const uint32_t*)(smem + OFF_KLO + kb);
                uint32_t bl1 = *(const uint32_t*)(smem + OFF_KLO + kb + 16);
                mma16816(c, qfh[kk], bh0, bh1);
                mma16816(c, qfh[kk], bl0, bl1);
                mma16816(c, qfl[kk], bh0, bh1);
            }
            int bit = (nb & 3) * 8 + 2 * tig;
            unsigned w0 = mw0[nb >> 2], w1 = mw1[nb >> 2];
            if ((w0 >> bit) & 1u)       lsum0 += __expf(c[0]);
            if ((w0 >> (bit + 1)) & 1u) lsum0 += __expf(c[1]);
            if ((w1 >> bit) & 1u)       lsum1 += __expf(c[2]);
            if ((w1 >> (bit + 1)) & 1u) lsum1 += __expf(c[3]);
        }
        __syncthreads();
    }
    lsum0 += __shfl_xor_sync(0xffffffffu, lsum0, 1);
    lsum0 += __shfl_xor_sync(0xffffffffu, lsum0, 2);
    lsum1 += __shfl_xor_sync(0xffffffffu, lsum1, 1);
    lsum1 += __shfl_xor_sync(0xffffffffu, lsum1, 2);
    float rinv0 = (lsum0 > 0.f) ? 1.f / lsum0 : 0.f;
    float rinv1 = (lsum1 > 0.f) ? 1.f / lsum1 : 0.f;

    // ================ phase 2: attn write + PV (interleaved per 16-col chunk) =
    float o[8][4];
    #pragma unroll
    for (int nd = 0; nd < 8; ++nd)
        #pragma unroll
        for (int j = 0; j < 4; ++j) o[nd][j] = 0.f;

    for (int kt = 0; kt < NKT; ++kt) {
        load_k_tiles(smem, bh, kt, tid);
        load_v_tiles(smem, bh, kt, tid);
        __syncthreads();
        unsigned mw0[4], mw1[4];
        #pragma unroll
        for (int qd = 0; qd < 4; ++qd) { mw0[qd] = mrow0[kt * 4 + qd]; mw1[qd] = mrow1[kt * 4 + qd]; }

        float* arow0 = attn ? attn + ((long long)bh * Sc + qrow0) * Sc + kt * 128 : (float*)0;

        #pragma unroll
        for (int kc = 0; kc < 8; ++kc) {
            uint32_t aH[4], aL[4];
            #pragma unroll
            for (int hh = 0; hh < 2; ++hh) {
                const int nb = 2 * kc + hh;
                float c[4] = {0.f, 0.f, 0.f, 0.f};
                #pragma unroll
                for (int kk = 0; kk < 4; ++kk) {
                    int kb = (nb * 8 + gid) * KROW + (kk * 16 + 2 * tig) * 2;
                    uint32_t bh0 = *(const uint32_t*)(smem + OFF_KHI + kb);
                    uint32_t bh1 = *(const uint32_t*)(smem + OFF_KHI + kb + 16);
                    uint32_t bl0 = *(const uint32_t*)(smem + OFF_KLO + kb);
                    uint32_t bl1 = *(const uint32_t*)(smem + OFF_KLO + kb + 16);
                    mma16816(c, qfh[kk], bh0, bh1);
                    mma16816(c, qfh[kk], bl0, bl1);
                    mma16816(c, qfl[kk], bh0, bh1);
                }
                int bit = (nb & 3) * 8 + 2 * tig;
                unsigned w0 = mw0[nb >> 2], w1 = mw1[nb >> 2];
                float p0 = ((w0 >> bit) & 1u)       ? __expf(c[0]) * rinv0 : 0.f;
                float p1 = ((w0 >> (bit + 1)) & 1u) ? __expf(c[1]) * rinv0 : 0.f;
                float p2 = ((w1 >> bit) & 1u)       ? __expf(c[2]) * rinv1 : 0.f;
                float p3 = ((w1 >> (bit + 1)) & 1u) ? __expf(c[3]) * rinv1 : 0.f;
                if (arow0) {
                    int cc = nb * 8 + 2 * tig;
                    *(float2*)(arow0 + cc)           = make_float2(p0, p1);
                    *(float2*)(arow0 + 8 * Sc + cc)  = make_float2(p2, p3);
                }
                float h0 = __bfloat162float(__float2bfloat16(p0));
                float h1 = __bfloat162float(__float2bfloat16(p1));
                float h2 = __bfloat162float(__float2bfloat16(p2));
                float h3 = __bfloat162float(__float2bfloat16(p3));
                aH[2 * hh + 0] = pk2(h0, h1);
                aH[2 * hh + 1] = pk2(h2, h3);
                aL[2 * hh + 0] = pk2(p0 - h0, p1 - h1);
                aL[2 * hh + 1] = pk2(p2 - h2, p3 - h3);
            }
            // PV for this 16-wide k-chunk
            #pragma unroll
            for (int nd = 0; nd < 8; ++nd) {
                int vb = (nd * 8 + gid) * VROW + (kc * 16 + 2 * tig) * 2;
                uint32_t bh0 = *(const uint32_t*)(smem + OFF_VHI + vb);
                uint32_t bh1 = *(const uint32_t*)(smem + OFF_VHI + vb + 16);
                uint32_t bl0 = *(const uint32_t*)(smem + OFF_VLO + vb);
                uint32_t bl1 = *(const uint32_t*)(smem + OFF_VLO + vb + 16);
                mma16816(o[nd], aH, bh0, bh1);
                mma16816(o[nd], aH, bl0, bl1);
                mma16816(o[nd], aL, bh0, bh1);
            }
        }
        __syncthreads();
    }

    // ================ write O ================
    {
        float* orow = out + ((long long)bh * Sc + qrow0) * Dc;
        #pragma unroll
        for (int nd = 0; nd < 8; ++nd) {
            int cc = nd * 8 + 2 * tig;
            *(float2*)(orow + cc)            = make_float2(o[nd][0], o[nd][1]);
            *(float2*)(orow + 8 * Dc + cc)   = make_float2(o[nd][2], o[nd][3]);
        }
    }
}

// ---------------- launcher ----------------
extern "C" void kernel_launch(void* const* d_in, const int* in_sizes, int n_in,
                              void* d_out, int out_size) {
    const float* q = (const float*)d_in[0];
    const float* k = (const float*)d_in[1];
    const float* v = (const float*)d_in[2];
    const int*   m = (const int*)d_in[3];
    float* out  = (float*)d_out;
    float* attn = ((long long)out_size >= OUT_ELEMS + ATTN_ELEMS) ? out + OUT_ELEMS : (float*)0;

    cudaFuncSetAttribute(attn_main_kernel,
                         cudaFuncAttributeMaxDynamicSharedMemorySize, SMEM_BYTES);

    conv_qk_kernel<<<QKD / 256, 256>>>(q, k);
    conv_v_kernel<<<BHc * (Sc / 64), 256>>>(v);
    pack_mask_kernel<<<MASKW / 256, 256>>>(m);
    attn_main_kernel<<<dim3(NQT, BHc), 128, SMEM_BYTES>>>(out, attn);
}

// round 8
// speedup vs baseline: 1.0649x; 1.0649x over previous
#include <cuda_runtime.h>
#include <cuda_bf16.h>
#include <cstdint>

#define DEVINL __device__ __forceinline__

// ---------------- problem constants ----------------
constexpr int Sc = 2048, Dc = 64, BHc = 32;
constexpr int NKT = Sc / 128;                 // 16 k-tiles
constexpr int QKD = BHc * Sc * Dc;            // 4194304
constexpr int MASKW = Sc * Sc / 32;           // 131072
constexpr long long OUT_ELEMS  = (long long)QKD;
constexpr long long ATTN_ELEMS = (long long)BHc * Sc * Sc;

// ---------------- static device scratch ----------------
__device__ __nv_bfloat16 g_Qhi[QKD], g_Qlo[QKD], g_Khi[QKD], g_Klo[QKD];
__device__ __nv_bfloat16 g_Vthi[QKD], g_Vtlo[QKD];   // transposed: [bh][d][s]
__device__ unsigned g_maskbits[MASKW];

// ---------------- smem layout (padded rows, conflict-free LDS) -------------
constexpr int KROW = 144;                    // 64 bf16 (128B) + 16B pad
constexpr int VROW = 272;                    // 128 bf16 (256B) + 16B pad
constexpr int OFF_KHI = 0;
constexpr int OFF_KLO = 128 * KROW;          // 18432
constexpr int OFF_VHI = 2 * 128 * KROW;      // 36864
constexpr int OFF_VLO = OFF_VHI + 64 * VROW;
constexpr int OFF_RINV = OFF_VLO + 64 * VROW;      // 128 floats
constexpr int SMEM_BYTES = OFF_RINV + 512;         // 72192

// ---------------- mma helpers ----------------
DEVINL void mma16816(float c[4], const uint32_t a[4], uint32_t b0, uint32_t b1) {
    asm volatile(
        "mma.sync.aligned.m16n8k16.row.col.f32.bf16.bf16.f32 "
        "{%0,%1,%2,%3}, {%4,%5,%6,%7}, {%8,%9}, {%0,%1,%2,%3};"
        : "+f"(c[0]), "+f"(c[1]), "+f"(c[2]), "+f"(c[3])
        : "r"(a[0]), "r"(a[1]), "r"(a[2]), "r"(a[3]), "r"(b0), "r"(b1));
}
DEVINL uint32_t pk2(float x, float y) {
    __nv_bfloat162 t = __floats2bfloat162_rn(x, y);
    return *(uint32_t*)&t;   // x in low half
}

// ---------------- preprocessing ----------------
// q is pre-scaled by 1/8 (=1/sqrt(64)) so the hot loop does exp(c) directly.
__global__ void conv_qk_kernel(const float* __restrict__ q, const float* __restrict__ k) {
    int i = blockIdx.x * 256 + threadIdx.x;
    float qv = q[i] * 0.125f;
    __nv_bfloat16 qh = __float2bfloat16(qv);
    g_Qhi[i] = qh;
    g_Qlo[i] = __float2bfloat16(qv - __bfloat162float(qh));
    float kv = k[i];
    __nv_bfloat16 kh = __float2bfloat16(kv);
    g_Khi[i] = kh;
    g_Klo[i] = __float2bfloat16(kv - __bfloat162float(kh));
}

// tiled transpose v[bh,s,d] -> g_Vt[bh,d,s] hi/lo
__global__ void conv_v_kernel(const float* __restrict__ v) {
    __shared__ float tile[64][65];
    int bh = blockIdx.x >> 5;
    int s0 = (blockIdx.x & 31) * 64;
    int tid = threadIdx.x;
    for (int i = tid; i < 64 * 64; i += 256) {
        int sr = i >> 6, dc = i & 63;
        tile[sr][dc] = v[((long long)bh * Sc + s0 + sr) * Dc + dc];
    }
    __syncthreads();
    for (int i = tid; i < 64 * 64; i += 256) {
        int dr = i >> 6, sc = i & 63;
        float vv = tile[sc][dr];
        __nv_bfloat16 vh = __float2bfloat16(vv);
        long long gi = ((long long)bh * Dc + dr) * Sc + s0 + sc;
        g_Vthi[gi] = vh;
        g_Vtlo[gi] = __float2bfloat16(vv - __bfloat162float(vh));
    }
}

__global__ void pack_mask_kernel(const int* __restrict__ m) {
    int i = blockIdx.x * 256 + threadIdx.x;     // row = i>>6, word = i&63
    int row = i >> 6, w = i & 63;
    const int4* p = (const int4*)(m + (long long)row * Sc + w * 32);
    unsigned bits = 0;
    #pragma unroll
    for (int g = 0; g < 8; ++g) {
        int4 x = p[g];
        bits |= (unsigned)(x.x != 0) << (g * 4 + 0);
        bits |= (unsigned)(x.y != 0) << (g * 4 + 1);
        bits |= (unsigned)(x.z != 0) << (g * 4 + 2);
        bits |= (unsigned)(x.w != 0) << (g * 4 + 3);
    }
    g_maskbits[i] = bits;
}

// ---------------- tile loaders (gmem -> padded smem) ----------------
DEVINL void load_k_tiles(char* smem, int bh, int kt, int tid) {
    const uint4* kh = (const uint4*)g_Khi + ((long long)bh * Sc + kt * 128) * 8;
    const uint4* kl = (const uint4*)g_Klo + ((long long)bh * Sc + kt * 128) * 8;
    #pragma unroll
    for (int i = tid; i < 128 * 8; i += 256) {
        int r = i >> 3, w = i & 7;
        int off = r * KROW + w * 16;
        *(uint4*)(smem + OFF_KHI + off) = kh[i];
        *(uint4*)(smem + OFF_KLO + off) = kl[i];
    }
}
DEVINL void load_v_tiles(char* smem, int bh, int kt, int tid) {
    const uint4* vh = (const uint4*)g_Vthi;
    const uint4* vl = (const uint4*)g_Vtlo;
    #pragma unroll
    for (int i = tid; i < 64 * 16; i += 256) {
        int d = i >> 4, w = i & 15;
        int off = d * VROW + w * 16;
        long long gi = ((long long)bh * 64 + d) * 256 + kt * 16 + w;
        *(uint4*)(smem + OFF_VHI + off) = vh[gi];
        *(uint4*)(smem + OFF_VLO + off) = vl[gi];
    }
}

// ---------------- main fused kernel (single pass, deferred norm) -----------
__global__ void __launch_bounds__(256, 1)
attn_main_kernel(float* __restrict__ out, float* __restrict__ attn) {
    extern __shared__ __align__(16) char smem[];
    const int qt = blockIdx.x;             // 0..15
    const int bh = blockIdx.y;             // 0..31
    const int tid = threadIdx.x;
    const int wid = tid >> 5, lane = tid & 31;
    const int gid = lane >> 2, tig = lane & 3;
    const int r0 = wid * 16 + gid;         // q-row (block-local), second row r0+8
    const long long qrow0 = (long long)qt * 128 + r0;

    // ---- stage Q tile into K region, pull A-fragments to registers ----
    {
        const uint4* qh = (const uint4*)g_Qhi + ((long long)bh * Sc + qt * 128) * 8;
        const uint4* ql = (const uint4*)g_Qlo + ((long long)bh * Sc + qt * 128) * 8;
        #pragma unroll
        for (int i = tid; i < 128 * 8; i += 256) {
            int r = i >> 3, w = i & 7;
            int off = r * KROW + w * 16;
            *(uint4*)(smem + OFF_KHI + off) = qh[i];
            *(uint4*)(smem + OFF_KLO + off) = ql[i];
        }
    }
    __syncthreads();
    uint32_t qfh[4][4], qfl[4][4];
    #pragma unroll
    for (int kk = 0; kk < 4; ++kk) {
        int base = r0 * KROW + (kk * 16 + 2 * tig) * 2;
        qfh[kk][0] = *(const uint32_t*)(smem + OFF_KHI + base);
        qfh[kk][1] = *(const uint32_t*)(smem + OFF_KHI + base + 8 * KROW);
        qfh[kk][2] = *(const uint32_t*)(smem + OFF_KHI + base + 16);
        qfh[kk][3] = *(const uint32_t*)(smem + OFF_KHI + base + 8 * KROW + 16);
        qfl[kk][0] = *(const uint32_t*)(smem + OFF_KLO + base);
        qfl[kk][1] = *(const uint32_t*)(smem + OFF_KLO + base + 8 * KROW);
        qfl[kk][2] = *(const uint32_t*)(smem + OFF_KLO + base + 16);
        qfl[kk][3] = *(const uint32_t*)(smem + OFF_KLO + base + 8 * KROW + 16);
    }
    __syncthreads();

    const unsigned* mrow0 = g_maskbits + (long long)qrow0 * 64;
    const unsigned* mrow1 = mrow0 + 8 * 64;

    float lsum0 = 0.f, lsum1 = 0.f;
    float o[8][4];
    #pragma unroll
    for (int nd = 0; nd < 8; ++nd)
        #pragma unroll
        for (int j = 0; j < 4; ++j) o[nd][j] = 0.f;

    // ================ single pass: QK + exp + attn(unnorm) + lsum + PV ======
    for (int kt = 0; kt < NKT; ++kt) {
        load_k_tiles(smem, bh, kt, tid);
        load_v_tiles(smem, bh, kt, tid);
        __syncthreads();
        unsigned mw0[4], mw1[4];
        #pragma unroll
        for (int qd = 0; qd < 4; ++qd) { mw0[qd] = mrow0[kt * 4 + qd]; mw1[qd] = mrow1[kt * 4 + qd]; }

        float* arow0 = attn ? attn + ((long long)bh * Sc + qrow0) * Sc + kt * 128 : (float*)0;

        #pragma unroll
        for (int kc = 0; kc < 8; ++kc) {
            uint32_t aH[4], aL[4];
            #pragma unroll
            for (int hh = 0; hh < 2; ++hh) {
                const int nb = 2 * kc + hh;
                float c1[4] = {0.f, 0.f, 0.f, 0.f};
                float c2[4] = {0.f, 0.f, 0.f, 0.f};
                #pragma unroll
                for (int kk = 0; kk < 4; ++kk) {
                    int kb = (nb * 8 + gid) * KROW + (kk * 16 + 2 * tig) * 2;
                    uint32_t bh0 = *(const uint32_t*)(smem + OFF_KHI + kb);
                    uint32_t bh1 = *(const uint32_t*)(smem + OFF_KHI + kb + 16);
                    uint32_t bl0 = *(const uint32_t*)(smem + OFF_KLO + kb);
                    uint32_t bl1 = *(const uint32_t*)(smem + OFF_KLO + kb + 16);
                    mma16816(c1, qfh[kk], bh0, bh1);
                    mma16816(c2, qfh[kk], bl0, bl1);
                    mma16816(c2, qfl[kk], bh0, bh1);
                }
                int bit = (nb & 3) * 8 + 2 * tig;
                unsigned w0 = mw0[nb >> 2], w1 = mw1[nb >> 2];
                float p0 = ((w0 >> bit) & 1u)       ? __expf(c1[0] + c2[0]) : 0.f;
                float p1 = ((w0 >> (bit + 1)) & 1u) ? __expf(c1[1] + c2[1]) : 0.f;
                float p2 = ((w1 >> bit) & 1u)       ? __expf(c1[2] + c2[2]) : 0.f;
                float p3 = ((w1 >> (bit + 1)) & 1u) ? __expf(c1[3] + c2[3]) : 0.f;
                lsum0 += p0 + p1;
                lsum1 += p2 + p3;
                if (arow0) {
                    int cc = nb * 8 + 2 * tig;
                    *(float2*)(arow0 + cc)           = make_float2(p0, p1);
                    *(float2*)(arow0 + 8 * Sc + cc)  = make_float2(p2, p3);
                }
                float h0 = __bfloat162float(__float2bfloat16(p0));
                float h1 = __bfloat162float(__float2bfloat16(p1));
                float h2 = __bfloat162float(__float2bfloat16(p2));
                float h3 = __bfloat162float(__float2bfloat16(p3));
                aH[2 * hh + 0] = pk2(h0, h1);
                aH[2 * hh + 1] = pk2(h2, h3);
                aL[2 * hh + 0] = pk2(p0 - h0, p1 - h1);
                aL[2 * hh + 1] = pk2(p2 - h2, p3 - h3);
            }
            // PV for this 16-wide k-chunk (unnormalized P)
            #pragma unroll
            for (int nd = 0; nd < 8; ++nd) {
                int vb = (nd * 8 + gid) * VROW + (kc * 16 + 2 * tig) * 2;
                uint32_t bh0 = *(const uint32_t*)(smem + OFF_VHI + vb);
                uint32_t bh1 = *(const uint32_t*)(smem + OFF_VHI + vb + 16);
                uint32_t bl0 = *(const uint32_t*)(smem + OFF_VLO + vb);
                uint32_t bl1 = *(const uint32_t*)(smem + OFF_VLO + vb + 16);
                mma16816(o[nd], aH, bh0, bh1);
                mma16816(o[nd], aH, bl0, bl1);
                mma16816(o[nd], aL, bh0, bh1);
            }
        }
        __syncthreads();
    }

    // ---- reduce row sums across quad, compute rinv ----
    lsum0 += __shfl_xor_sync(0xffffffffu, lsum0, 1);
    lsum0 += __shfl_xor_sync(0xffffffffu, lsum0, 2);
    lsum1 += __shfl_xor_sync(0xffffffffu, lsum1, 1);
    lsum1 += __shfl_xor_sync(0xffffffffu, lsum1, 2);
    float rinv0 = (lsum0 > 0.f) ? 1.f / lsum0 : 0.f;
    float rinv1 = (lsum1 > 0.f) ? 1.f / lsum1 : 0.f;

    // ---- write O (normalized in registers) ----
    {
        float* orow = out + ((long long)bh * Sc + qrow0) * Dc;
        #pragma unroll
        for (int nd = 0; nd < 8; ++nd) {
            int cc = nd * 8 + 2 * tig;
            *(float2*)(orow + cc)          = make_float2(o[nd][0] * rinv0, o[nd][1] * rinv0);
            *(float2*)(orow + 8 * Dc + cc) = make_float2(o[nd][2] * rinv1, o[nd][3] * rinv1);
        }
    }

    // ---- rescale this CTA's attn block (gmem read-modify-write) ----
    if (attn) {
        float* srow = (float*)(smem + OFF_RINV);
        if (tig == 0) { srow[r0] = rinv0; srow[r0 + 8] = rinv1; }
        __syncthreads();
        float4* base = (float4*)(attn + ((long long)bh * Sc + (long long)qt * 128) * Sc);
        #pragma unroll 4
        for (int i = tid; i < 128 * 512; i += 256) {
            int row = i >> 9, c4 = i & 511;
            float s = srow[row];
            float4 v = base[row * 512 + c4];
            v.x *= s; v.y *= s; v.z *= s; v.w *= s;
            base[row * 512 + c4] = v;
        }
    }
}

// ---------------- launcher ----------------
extern "C" void kernel_launch(void* const* d_in, const int* in_sizes, int n_in,
                              void* d_out, int out_size) {
    const float* q = (const float*)d_in[0];
    const float* k = (const float*)d_in[1];
    const float* v = (const float*)d_in[2];
    const int*   m = (const int*)d_in[3];
    float* out  = (float*)d_out;
    float* attn = ((long long)out_size >= OUT_ELEMS + ATTN_ELEMS) ? out + OUT_ELEMS : (float*)0;

    cudaFuncSetAttribute(attn_main_kernel,
                         cudaFuncAttributeMaxDynamicSharedMemorySize, SMEM_BYTES);

    conv_qk_kernel<<<QKD / 256, 256>>>(q, k);
    conv_v_kernel<<<BHc * (Sc / 64), 256>>>(v);
    pack_mask_kernel<<<MASKW / 256, 256>>>(m);
    attn_main_kernel<<<dim3(NKT, BHc), 256, SMEM_BYTES>>>(out, attn);
}

// round 9
// speedup vs baseline: 1.0729x; 1.0075x over previous
#include <cuda_runtime.h>
#include <cuda_bf16.h>
#include <cstdint>

#define DEVINL __device__ __forceinline__

// ---------------- problem constants ----------------
constexpr int Sc = 2048, Dc = 64, BHc = 32;
constexpr int NKT = Sc / 128;                 // 16 k-tiles
constexpr int QKD = BHc * Sc * Dc;            // 4194304
constexpr int MASKW = Sc * Sc / 32;           // 131072
constexpr long long OUT_ELEMS  = (long long)QKD;
constexpr long long ATTN_ELEMS = (long long)BHc * Sc * Sc;

// ---------------- static device scratch ----------------
__device__ __nv_bfloat16 g_Qhi[QKD], g_Qlo[QKD], g_Khi[QKD], g_Klo[QKD];
__device__ __nv_bfloat16 g_Vthi[QKD], g_Vtlo[QKD];   // transposed: [bh][d][s]
__device__ unsigned g_maskbits[MASKW];

// ---------------- smem layout: double-buffered stages ----------------------
constexpr int KROW = 144;                    // 64 bf16 (128B) + 16B pad
constexpr int VROW = 272;                    // 128 bf16 (256B) + 16B pad
constexpr int OFF_KHI = 0;
constexpr int OFF_KLO = 128 * KROW;          // 18432
constexpr int OFF_VHI = 2 * 128 * KROW;      // 36864
constexpr int OFF_VLO = OFF_VHI + 64 * VROW; // 54272
constexpr int STAGE   = OFF_VLO + 64 * VROW; // 71680 per stage
constexpr int OFF_RINV = 2 * STAGE;          // 143360
constexpr int SMEM_BYTES = OFF_RINV + 512;   // 143872

// ---------------- asm helpers ----------------
DEVINL void mma16816(float c[4], const uint32_t a[4], uint32_t b0, uint32_t b1) {
    asm volatile(
        "mma.sync.aligned.m16n8k16.row.col.f32.bf16.bf16.f32 "
        "{%0,%1,%2,%3}, {%4,%5,%6,%7}, {%8,%9}, {%0,%1,%2,%3};"
        : "+f"(c[0]), "+f"(c[1]), "+f"(c[2]), "+f"(c[3])
        : "r"(a[0]), "r"(a[1]), "r"(a[2]), "r"(a[3]), "r"(b0), "r"(b1));
}
DEVINL uint32_t pk2(float x, float y) {
    __nv_bfloat162 t = __floats2bfloat162_rn(x, y);
    return *(uint32_t*)&t;   // x in low half
}
DEVINL uint32_t smem_u32(const void* p) {
    uint32_t a;
    asm("{ .reg .u64 t; cvta.to.shared.u64 t, %1; cvt.u32.u64 %0, t; }" : "=r"(a) : "l"(p));
    return a;
}
DEVINL void cp_async16(uint32_t dst, const void* src) {
    asm volatile("cp.async.cg.shared.global [%0], [%1], 16;" :: "r"(dst), "l"(src));
}
#define CP_COMMIT()  asm volatile("cp.async.commit_group;" ::: "memory")
#define CP_WAIT(n)   asm volatile("cp.async.wait_group %0;" :: "n"(n) : "memory")

// ---------------- preprocessing ----------------
// q pre-scaled by 1/8 (=1/sqrt(64)) so the hot loop does exp(c) directly.
__global__ void conv_qk_kernel(const float* __restrict__ q, const float* __restrict__ k) {
    int i = blockIdx.x * 256 + threadIdx.x;
    float qv = q[i] * 0.125f;
    __nv_bfloat16 qh = __float2bfloat16(qv);
    g_Qhi[i] = qh;
    g_Qlo[i] = __float2bfloat16(qv - __bfloat162float(qh));
    float kv = k[i];
    __nv_bfloat16 kh = __float2bfloat16(kv);
    g_Khi[i] = kh;
    g_Klo[i] = __float2bfloat16(kv - __bfloat162float(kh));
}

// tiled transpose v[bh,s,d] -> g_Vt[bh,d,s] hi/lo
__global__ void conv_v_kernel(const float* __restrict__ v) {
    __shared__ float tile[64][65];
    int bh = blockIdx.x >> 5;
    int s0 = (blockIdx.x & 31) * 64;
    int tid = threadIdx.x;
    for (int i = tid; i < 64 * 64; i += 256) {
        int sr = i >> 6, dc = i & 63;
        tile[sr][dc] = v[((long long)bh * Sc + s0 + sr) * Dc + dc];
    }
    __syncthreads();
    for (int i = tid; i < 64 * 64; i += 256) {
        int dr = i >> 6, sc = i & 63;
        float vv = tile[sc][dr];
        __nv_bfloat16 vh = __float2bfloat16(vv);
        long long gi = ((long long)bh * Dc + dr) * Sc + s0 + sc;
        g_Vthi[gi] = vh;
        g_Vtlo[gi] = __float2bfloat16(vv - __bfloat162float(vh));
    }
}

__global__ void pack_mask_kernel(const int* __restrict__ m) {
    int i = blockIdx.x * 256 + threadIdx.x;     // row = i>>6, word = i&63
    int row = i >> 6, w = i & 63;
    const int4* p = (const int4*)(m + (long long)row * Sc + w * 32);
    unsigned bits = 0;
    #pragma unroll
    for (int g = 0; g < 8; ++g) {
        int4 x = p[g];
        bits |= (unsigned)(x.x != 0) << (g * 4 + 0);
        bits |= (unsigned)(x.y != 0) << (g * 4 + 1);
        bits |= (unsigned)(x.z != 0) << (g * 4 + 2);
        bits |= (unsigned)(x.w != 0) << (g * 4 + 3);
    }
    g_maskbits[i] = bits;
}

// ---------------- cp.async tile prefetch (no register staging) -------------
DEVINL void preload_tiles(uint32_t smb_stage, int bh, int kt, int tid) {
    const uint4* kh = (const uint4*)g_Khi + ((long long)bh * Sc + kt * 128) * 8;
    const uint4* kl = (const uint4*)g_Klo + ((long long)bh * Sc + kt * 128) * 8;
    #pragma unroll
    for (int i = tid; i < 128 * 8; i += 256) {
        int r = i >> 3, w = i & 7;
        uint32_t off = (uint32_t)(r * KROW + w * 16);
        cp_async16(smb_stage + OFF_KHI + off, kh + i);
        cp_async16(smb_stage + OFF_KLO + off, kl + i);
    }
    const uint4* vh = (const uint4*)g_Vthi;
    const uint4* vl = (const uint4*)g_Vtlo;
    #pragma unroll
    for (int i = tid; i < 64 * 16; i += 256) {
        int d = i >> 4, w = i & 15;
        uint32_t off = (uint32_t)(d * VROW + w * 16);
        long long gi = ((long long)bh * 64 + d) * 256 + kt * 16 + w;
        cp_async16(smb_stage + OFF_VHI + off, vh + gi);
        cp_async16(smb_stage + OFF_VLO + off, vl + gi);
    }
}

// ---------------- main fused kernel (single pass + cp.async pipeline) ------
__global__ void __launch_bounds__(256, 1)
attn_main_kernel(float* __restrict__ out, float* __restrict__ attn) {
    extern __shared__ __align__(16) char smem[];
    const int qt = blockIdx.x;             // 0..15
    const int bh = blockIdx.y;             // 0..31
    const int tid = threadIdx.x;
    const int wid = tid >> 5, lane = tid & 31;
    const int gid = lane >> 2, tig = lane & 3;
    const int r0 = wid * 16 + gid;         // q-row (block-local), second row r0+8
    const long long qrow0 = (long long)qt * 128 + r0;
    const uint32_t smb = smem_u32(smem);

    // kick off prefetch of k-tile 0 into stage 0 immediately
    preload_tiles(smb + 0 * STAGE, bh, 0, tid);
    CP_COMMIT();

    // ---- stage Q tile into stage-1 K region, pull A-fragments to regs ----
    {
        const uint4* qh = (const uint4*)g_Qhi + ((long long)bh * Sc + qt * 128) * 8;
        const uint4* ql = (const uint4*)g_Qlo + ((long long)bh * Sc + qt * 128) * 8;
        for (int i = tid; i < 128 * 8; i += 256) {
            int r = i >> 3, w = i & 7;
            int off = STAGE + r * KROW + w * 16;
            *(uint4*)(smem + OFF_KHI + off) = qh[i];
            *(uint4*)(smem + OFF_KLO + off) = ql[i];
        }
    }
    __syncthreads();
    uint32_t qfh[4][4], qfl[4][4];
    #pragma unroll
    for (int kk = 0; kk < 4; ++kk) {
        int base = STAGE + r0 * KROW + (kk * 16 + 2 * tig) * 2;
        qfh[kk][0] = *(const uint32_t*)(smem + OFF_KHI + base);
        qfh[kk][1] = *(const uint32_t*)(smem + OFF_KHI + base + 8 * KROW);
        qfh[kk][2] = *(const uint32_t*)(smem + OFF_KHI + base + 16);
        qfh[kk][3] = *(const uint32_t*)(smem + OFF_KHI + base + 8 * KROW + 16);
        qfl[kk][0] = *(const uint32_t*)(smem + OFF_KLO + base);
        qfl[kk][1] = *(const uint32_t*)(smem + OFF_KLO + base + 8 * KROW);
        qfl[kk][2] = *(const uint32_t*)(smem + OFF_KLO + base + 16);
        qfl[kk][3] = *(const uint32_t*)(smem + OFF_KLO + base + 8 * KROW + 16);
    }
    __syncthreads();   // everyone done reading Q before stage 1 is reused

    const unsigned* mrow0 = g_maskbits + (long long)qrow0 * 64;
    const unsigned* mrow1 = mrow0 + 8 * 64;

    float lsum0 = 0.f, lsum1 = 0.f;
    float o[8][4];
    #pragma unroll
    for (int nd = 0; nd < 8; ++nd)
        #pragma unroll
        for (int j = 0; j < 4; ++j) o[nd][j] = 0.f;

    // ================ single pass: QK + exp + attn(unnorm) + lsum + PV ======
    for (int kt = 0; kt < NKT; ++kt) {
        if (kt + 1 < NKT) {
            preload_tiles(smb + ((kt + 1) & 1) * STAGE, bh, kt + 1, tid);
            CP_COMMIT();
            CP_WAIT(1);
        } else {
            CP_WAIT(0);
        }
        __syncthreads();
        const char* buf = smem + (kt & 1) * STAGE;

        unsigned mw0[4], mw1[4];
        #pragma unroll
        for (int qd = 0; qd < 4; ++qd) { mw0[qd] = mrow0[kt * 4 + qd]; mw1[qd] = mrow1[kt * 4 + qd]; }

        float* arow0 = attn ? attn + ((long long)bh * Sc + qrow0) * Sc + kt * 128 : (float*)0;

        #pragma unroll
        for (int kc = 0; kc < 8; ++kc) {
            uint32_t aH[4], aL[4];
            #pragma unroll
            for (int hh = 0; hh < 2; ++hh) {
                const int nb = 2 * kc + hh;
                float c1[4] = {0.f, 0.f, 0.f, 0.f};
                float c2[4] = {0.f, 0.f, 0.f, 0.f};
                #pragma unroll
                for (int kk = 0; kk < 4; ++kk) {
                    int kb = (nb * 8 + gid) * KROW + (kk * 16 + 2 * tig) * 2;
                    uint32_t bh0 = *(const uint32_t*)(buf + OFF_KHI + kb);
                    uint32_t bh1 = *(const uint32_t*)(buf + OFF_KHI + kb + 16);
                    uint32_t bl0 = *(const uint32_t*)(buf + OFF_KLO + kb);
                    uint32_t bl1 = *(const uint32_t*)(buf + OFF_KLO + kb + 16);
                    mma16816(c1, qfh[kk], bh0, bh1);
                    mma16816(c2, qfh[kk], bl0, bl1);
                    mma16816(c2, qfl[kk], bh0, bh1);
                }
                int bit = (nb & 3) * 8 + 2 * tig;
                unsigned w0 = mw0[nb >> 2], w1 = mw1[nb >> 2];
                float p0 = ((w0 >> bit) & 1u)       ? __expf(c1[0] + c2[0]) : 0.f;
                float p1 = ((w0 >> (bit + 1)) & 1u) ? __expf(c1[1] + c2[1]) : 0.f;
                float p2 = ((w1 >> bit) & 1u)       ? __expf(c1[2] + c2[2]) : 0.f;
                float p3 = ((w1 >> (bit + 1)) & 1u) ? __expf(c1[3] + c2[3]) : 0.f;
                lsum0 += p0 + p1;
                lsum1 += p2 + p3;
                if (arow0) {
                    int cc = nb * 8 + 2 * tig;
                    *(float2*)(arow0 + cc)           = make_float2(p0, p1);
                    *(float2*)(arow0 + 8 * Sc + cc)  = make_float2(p2, p3);
                }
                float h0 = __bfloat162float(__float2bfloat16(p0));
                float h1 = __bfloat162float(__float2bfloat16(p1));
                float h2 = __bfloat162float(__float2bfloat16(p2));
                float h3 = __bfloat162float(__float2bfloat16(p3));
                aH[2 * hh + 0] = pk2(h0, h1);
                aH[2 * hh + 1] = pk2(h2, h3);
                aL[2 * hh + 0] = pk2(p0 - h0, p1 - h1);
                aL[2 * hh + 1] = pk2(p2 - h2, p3 - h3);
            }
            // PV for this 16-wide k-chunk (unnormalized P)
            #pragma unroll
            for (int nd = 0; nd < 8; ++nd) {
                int vb = (nd * 8 + gid) * VROW + (kc * 16 + 2 * tig) * 2;
                uint32_t bh0 = *(const uint32_t*)(buf + OFF_VHI + vb);
                uint32_t bh1 = *(const uint32_t*)(buf + OFF_VHI + vb + 16);
                uint32_t bl0 = *(const uint32_t*)(buf + OFF_VLO + vb);
                uint32_t bl1 = *(const uint32_t*)(buf + OFF_VLO + vb + 16);
                mma16816(o[nd], aH, bh0, bh1);
                mma16816(o[nd], aH, bl0, bl1);
                mma16816(o[nd], aL, bh0, bh1);
            }
        }
        __syncthreads();   // all reads of buf done before it is re-filled
    }

    // ---- reduce row sums across quad, compute rinv ----
    lsum0 += __shfl_xor_sync(0xffffffffu, lsum0, 1);
    lsum0 += __shfl_xor_sync(0xffffffffu, lsum0, 2);
    lsum1 += __shfl_xor_sync(0xffffffffu, lsum1, 1);
    lsum1 += __shfl_xor_sync(0xffffffffu, lsum1, 2);
    float rinv0 = (lsum0 > 0.f) ? 1.f / lsum0 : 0.f;
    float rinv1 = (lsum1 > 0.f) ? 1.f / lsum1 : 0.f;

    // ---- write O (normalized in registers) ----
    {
        float* orow = out + ((long long)bh * Sc + qrow0) * Dc;
        #pragma unroll
        for (int nd = 0; nd < 8; ++nd) {
            int cc = nd * 8 + 2 * tig;
            *(float2*)(orow + cc)          = make_float2(o[nd][0] * rinv0, o[nd][1] * rinv0);
            *(float2*)(orow + 8 * Dc + cc) = make_float2(o[nd][2] * rinv1, o[nd][3] * rinv1);
        }
    }

    // ---- rescale this CTA's attn block (gmem read-modify-write) ----
    if (attn) {
        float* srow = (float*)(smem + OFF_RINV);
        if (tig == 0) { srow[r0] = rinv0; srow[r0 + 8] = rinv1; }
        __syncthreads();
        float4* base = (float4*)(attn + ((long long)bh * Sc + (long long)qt * 128) * Sc);
        #pragma unroll 4
        for (int i = tid; i < 128 * 512; i += 256) {
            int row = i >> 9, c4 = i & 511;
            float s = srow[row];
            float4 v = base[row * 512 + c4];
            v.x *= s; v.y *= s; v.z *= s; v.w *= s;
            base[row * 512 + c4] = v;
        }
    }
}

// ---------------- launcher ----------------
extern "C" void kernel_launch(void* const* d_in, const int* in_sizes, int n_in,
                              void* d_out, int out_size) {
    const float* q = (const float*)d_in[0];
    const float* k = (const float*)d_in[1];
    const float* v = (const float*)d_in[2];
    const int*   m = (const int*)d_in[3];
    float* out  = (float*)d_out;
    float* attn = ((long long)out_size >= OUT_ELEMS + ATTN_ELEMS) ? out + OUT_ELEMS : (float*)0;

    cudaFuncSetAttribute(attn_main_kernel,
                         cudaFuncAttributeMaxDynamicSharedMemorySize, SMEM_BYTES);

    conv_qk_kernel<<<QKD / 256, 256>>>(q, k);
    conv_v_kernel<<<BHc * (Sc / 64), 256>>>(v);
    pack_mask_kernel<<<MASKW / 256, 256>>>(m);
    attn_main_kernel<<<dim3(NKT, BHc), 256, SMEM_BYTES>>>(out, attn);
}

// round 10
// speedup vs baseline: 1.6863x; 1.5718x over previous
#include <cuda_runtime.h>
#include <cuda_bf16.h>
#include <cstdint>

#define DEVINL __device__ __forceinline__

// ---------------- problem constants ----------------
constexpr int Sc = 2048, Dc = 64, BHc = 32;
constexpr int NKT = Sc / 128;                 // 16 k-tiles
constexpr int QKD = BHc * Sc * Dc;            // 4194304
constexpr int MASKW = Sc * Sc / 32;           // 131072
constexpr long long OUT_ELEMS  = (long long)QKD;
constexpr long long ATTN_ELEMS = (long long)BHc * Sc * Sc;

// ---------------- static device scratch ----------------
__device__ __nv_bfloat16 g_Qhi[QKD], g_Qlo[QKD], g_Khi[QKD], g_Klo[QKD];
__device__ __nv_bfloat16 g_Vthi[QKD], g_Vtlo[QKD];   // transposed: [bh][d][s]
__device__ unsigned g_maskbits[MASKW];

// ---------------- smem layout: K region (phase1) and V region (phase2) share
constexpr int KROW = 144;                    // 64 bf16 (128B) + 16B pad
constexpr int VROW = 272;                    // 128 bf16 (256B) + 16B pad
constexpr int OFF_KHI = 0;
constexpr int OFF_KLO = 128 * KROW;          // 18432
constexpr int OFF_VHI = 0;                   // reused after phase 1
constexpr int OFF_VLO = 64 * VROW;           // 17408
constexpr int SMEM_BYTES = 2 * 128 * KROW;   // 36864 (>= V region 34816)

// ---------------- asm helpers ----------------
DEVINL void mma16816(float c[4], const uint32_t a[4], uint32_t b0, uint32_t b1) {
    asm volatile(
        "mma.sync.aligned.m16n8k16.row.col.f32.bf16.bf16.f32 "
        "{%0,%1,%2,%3}, {%4,%5,%6,%7}, {%8,%9}, {%0,%1,%2,%3};"
        : "+f"(c[0]), "+f"(c[1]), "+f"(c[2]), "+f"(c[3])
        : "r"(a[0]), "r"(a[1]), "r"(a[2]), "r"(a[3]), "r"(b0), "r"(b1));
}
DEVINL uint32_t pk2(float x, float y) {
    __nv_bfloat162 t = __floats2bfloat162_rn(x, y);
    return *(uint32_t*)&t;   // x in low half
}

// ---------------- preprocessing ----------------
// q pre-scaled by 1/8 (=1/sqrt(64)) so the hot loop does exp(c) directly.
__global__ void conv_qk_kernel(const float* __restrict__ q, const float* __restrict__ k) {
    int i = blockIdx.x * 256 + threadIdx.x;
    float qv = q[i] * 0.125f;
    __nv_bfloat16 qh = __float2bfloat16(qv);
    g_Qhi[i] = qh;
    g_Qlo[i] = __float2bfloat16(qv - __bfloat162float(qh));
    float kv = k[i];
    __nv_bfloat16 kh = __float2bfloat16(kv);
    g_Khi[i] = kh;
    g_Klo[i] = __float2bfloat16(kv - __bfloat162float(kh));
}

// tiled transpose v[bh,s,d] -> g_Vt[bh,d,s] hi/lo
__global__ void conv_v_kernel(const float* __restrict__ v) {
    __shared__ float tile[64][65];
    int bh = blockIdx.x >> 5;
    int s0 = (blockIdx.x & 31) * 64;
    int tid = threadIdx.x;
    for (int i = tid; i < 64 * 64; i += 256) {
        int sr = i >> 6, dc = i & 63;
        tile[sr][dc] = v[((long long)bh * Sc + s0 + sr) * Dc + dc];
    }
    __syncthreads();
    for (int i = tid; i < 64 * 64; i += 256) {
        int dr = i >> 6, sc = i & 63;
        float vv = tile[sc][dr];
        __nv_bfloat16 vh = __float2bfloat16(vv);
        long long gi = ((long long)bh * Dc + dr) * Sc + s0 + sc;
        g_Vthi[gi] = vh;
        g_Vtlo[gi] = __float2bfloat16(vv - __bfloat162float(vh));
    }
}

__global__ void pack_mask_kernel(const int* __restrict__ m) {
    int i = blockIdx.x * 256 + threadIdx.x;     // row = i>>6, word = i&63
    int row = i >> 6, w = i & 63;
    const int4* p = (const int4*)(m + (long long)row * Sc + w * 32);
    unsigned bits = 0;
    #pragma unroll
    for (int g = 0; g < 8; ++g) {
        int4 x = p[g];
        bits |= (unsigned)(x.x != 0) << (g * 4 + 0);
        bits |= (unsigned)(x.y != 0) << (g * 4 + 1);
        bits |= (unsigned)(x.z != 0) << (g * 4 + 2);
        bits |= (unsigned)(x.w != 0) << (g * 4 + 3);
    }
    g_maskbits[i] = bits;
}

// ---------------- tile loaders ----------------
DEVINL void load_k_tiles(char* smem, int bh, int kt, int tid) {
    const uint4* kh = (const uint4*)g_Khi + ((long long)bh * Sc + kt * 128) * 8;
    const uint4* kl = (const uint4*)g_Klo + ((long long)bh * Sc + kt * 128) * 8;
    #pragma unroll
    for (int i = tid; i < 128 * 8; i += 256) {
        int r = i >> 3, w = i & 7;
        int off = r * KROW + w * 16;
        *(uint4*)(smem + OFF_KHI + off) = kh[i];
        *(uint4*)(smem + OFF_KLO + off) = kl[i];
    }
}
DEVINL void load_v_tiles(char* smem, int bh, int kt, int tid) {
    const uint4* vh = (const uint4*)g_Vthi;
    const uint4* vl = (const uint4*)g_Vtlo;
    #pragma unroll
    for (int i = tid; i < 64 * 16; i += 256) {
        int d = i >> 4, w = i & 15;
        int off = d * VROW + w * 16;
        long long gi = ((long long)bh * 64 + d) * 256 + kt * 16 + w;
        *(uint4*)(smem + OFF_VHI + off) = vh[gi];
        *(uint4*)(smem + OFF_VLO + off) = vl[gi];
    }
}

// ---------------- main fused kernel: two lean phases ----------------
__global__ void __launch_bounds__(256, 2)
attn_main_kernel(float* __restrict__ out, float* __restrict__ attn) {
    extern __shared__ __align__(16) char smem[];
    const int qt = blockIdx.x;             // 0..15
    const int bh = blockIdx.y;             // 0..31
    const int tid = threadIdx.x;
    const int wid = tid >> 5, lane = tid & 31;
    const int gid = lane >> 2, tig = lane & 3;
    const int r0 = wid * 16 + gid;         // q-row (block-local), second row r0+8
    const long long qrow0 = (long long)qt * 128 + r0;
    float* const abase = attn + ((long long)bh * Sc + qrow0) * Sc;   // row r0

    float lsum0 = 0.f, lsum1 = 0.f;

    // ================ PHASE 1: QK + exp -> attn (unnormalized) + lsum =======
    {
        // stage Q tile into K region, pull A-fragments to registers
        {
            const uint4* qh = (const uint4*)g_Qhi + ((long long)bh * Sc + qt * 128) * 8;
            const uint4* ql = (const uint4*)g_Qlo + ((long long)bh * Sc + qt * 128) * 8;
            #pragma unroll
            for (int i = tid; i < 128 * 8; i += 256) {
                int r = i >> 3, w = i & 7;
                int off = r * KROW + w * 16;
                *(uint4*)(smem + OFF_KHI + off) = qh[i];
                *(uint4*)(smem + OFF_KLO + off) = ql[i];
            }
        }
        __syncthreads();
        uint32_t qfh[4][4], qfl[4][4];
        #pragma unroll
        for (int kk = 0; kk < 4; ++kk) {
            int base = r0 * KROW + (kk * 16 + 2 * tig) * 2;
            qfh[kk][0] = *(const uint32_t*)(smem + OFF_KHI + base);
            qfh[kk][1] = *(const uint32_t*)(smem + OFF_KHI + base + 8 * KROW);
            qfh[kk][2] = *(const uint32_t*)(smem + OFF_KHI + base + 16);
            qfh[kk][3] = *(const uint32_t*)(smem + OFF_KHI + base + 8 * KROW + 16);
            qfl[kk][0] = *(const uint32_t*)(smem + OFF_KLO + base);
            qfl[kk][1] = *(const uint32_t*)(smem + OFF_KLO + base + 8 * KROW);
            qfl[kk][2] = *(const uint32_t*)(smem + OFF_KLO + base + 16);
            qfl[kk][3] = *(const uint32_t*)(smem + OFF_KLO + base + 8 * KROW + 16);
        }
        __syncthreads();

        const unsigned* mrow0 = g_maskbits + (long long)qrow0 * 64;
        const unsigned* mrow1 = mrow0 + 8 * 64;

        for (int kt = 0; kt < NKT; ++kt) {
            load_k_tiles(smem, bh, kt, tid);
            __syncthreads();
            unsigned mw0[4], mw1[4];
            #pragma unroll
            for (int qd = 0; qd < 4; ++qd) { mw0[qd] = mrow0[kt * 4 + qd]; mw1[qd] = mrow1[kt * 4 + qd]; }
            float* arow0 = abase + kt * 128;
            #pragma unroll
            for (int nb = 0; nb < 16; ++nb) {
                float c1[4] = {0.f, 0.f, 0.f, 0.f};
                float c2[4] = {0.f, 0.f, 0.f, 0.f};
                #pragma unroll
                for (int kk = 0; kk < 4; ++kk) {
                    int kb = (nb * 8 + gid) * KROW + (kk * 16 + 2 * tig) * 2;
                    uint32_t bh0 = *(const uint32_t*)(smem + OFF_KHI + kb);
                    uint32_t bh1 = *(const uint32_t*)(smem + OFF_KHI + kb + 16);
                    uint32_t bl0 = *(const uint32_t*)(smem + OFF_KLO + kb);
                    uint32_t bl1 = *(const uint32_t*)(smem + OFF_KLO + kb + 16);
                    mma16816(c1, qfh[kk], bh0, bh1);
                    mma16816(c2, qfh[kk], bl0, bl1);
                    mma16816(c2, qfl[kk], bh0, bh1);
                }
                int bit = (nb & 3) * 8 + 2 * tig;
                unsigned w0 = mw0[nb >> 2], w1 = mw1[nb >> 2];
                float p0 = ((w0 >> bit) & 1u)       ? __expf(c1[0] + c2[0]) : 0.f;
                float p1 = ((w0 >> (bit + 1)) & 1u) ? __expf(c1[1] + c2[1]) : 0.f;
                float p2 = ((w1 >> bit) & 1u)       ? __expf(c1[2] + c2[2]) : 0.f;
                float p3 = ((w1 >> (bit + 1)) & 1u) ? __expf(c1[3] + c2[3]) : 0.f;
                lsum0 += p0 + p1;
                lsum1 += p2 + p3;
                int cc = nb * 8 + 2 * tig;
                *(float2*)(arow0 + cc)          = make_float2(p0, p1);
                *(float2*)(arow0 + 8 * Sc + cc) = make_float2(p2, p3);
            }
            __syncthreads();
        }
    }

    // ---- reduce row sums across quad, compute rinv ----
    lsum0 += __shfl_xor_sync(0xffffffffu, lsum0, 1);
    lsum0 += __shfl_xor_sync(0xffffffffu, lsum0, 2);
    lsum1 += __shfl_xor_sync(0xffffffffu, lsum1, 1);
    lsum1 += __shfl_xor_sync(0xffffffffu, lsum1, 2);
    const float rinv0 = (lsum0 > 0.f) ? 1.f / lsum0 : 0.f;
    const float rinv1 = (lsum1 > 0.f) ? 1.f / lsum1 : 0.f;

    __syncthreads();   // orders phase-1 global writes before phase-2 reads (CTA scope)

    // ================ PHASE 2: read e, normalize+writeback, PV ==============
    float o[8][4];
    #pragma unroll
    for (int nd = 0; nd < 8; ++nd)
        #pragma unroll
        for (int j = 0; j < 4; ++j) o[nd][j] = 0.f;

    for (int kt = 0; kt < NKT; ++kt) {
        load_v_tiles(smem, bh, kt, tid);
        __syncthreads();
        float* arow0 = abase + kt * 128;

        // software pipeline: prefetch e-fragments one kc ahead
        float2 f0, f1, f2, f3;
        {
            int cc = 2 * tig;          // kc=0, nb=0 col base
            f0 = *(float2*)(arow0 + cc);
            f1 = *(float2*)(arow0 + 8 * Sc + cc);
            f2 = *(float2*)(arow0 + 8 + cc);
            f3 = *(float2*)(arow0 + 8 * Sc + 8 + cc);
        }
        #pragma unroll
        for (int kc = 0; kc < 8; ++kc) {
            float2 g0, g1, g2, g3;
            if (kc < 7) {
                int cc = (kc + 1) * 16 + 2 * tig;
                g0 = *(float2*)(arow0 + cc);
                g1 = *(float2*)(arow0 + 8 * Sc + cc);
                g2 = *(float2*)(arow0 + 8 + cc);
                g3 = *(float2*)(arow0 + 8 * Sc + 8 + cc);
            }
            // normalize
            float p0 = f0.x * rinv0, p1 = f0.y * rinv0;
            float p2 = f1.x * rinv1, p3 = f1.y * rinv1;
            float p4 = f2.x * rinv0, p5 = f2.y * rinv0;
            float p6 = f3.x * rinv1, p7 = f3.y * rinv1;
            // write back normalized attn
            {
                int cc = kc * 16 + 2 * tig;
                *(float2*)(arow0 + cc)              = make_float2(p0, p1);
                *(float2*)(arow0 + 8 * Sc + cc)     = make_float2(p2, p3);
                *(float2*)(arow0 + 8 + cc)          = make_float2(p4, p5);
                *(float2*)(arow0 + 8 * Sc + 8 + cc) = make_float2(p6, p7);
            }
            // pack bf16 hi/lo A-fragments
            uint32_t aH[4], aL[4];
            float h0 = __bfloat162float(__float2bfloat16(p0));
            float h1 = __bfloat162float(__float2bfloat16(p1));
            float h2 = __bfloat162float(__float2bfloat16(p2));
            float h3 = __bfloat162float(__float2bfloat16(p3));
            aH[0] = pk2(h0, h1); aH[1] = pk2(h2, h3);
            aL[0] = pk2(p0 - h0, p1 - h1); aL[1] = pk2(p2 - h2, p3 - h3);
            h0 = __bfloat162float(__float2bfloat16(p4));
            h1 = __bfloat162float(__float2bfloat16(p5));
            h2 = __bfloat162float(__float2bfloat16(p6));
            h3 = __bfloat162float(__float2bfloat16(p7));
            aH[2] = pk2(h0, h1); aH[3] = pk2(h2, h3);
            aL[2] = pk2(p4 - h0, p5 - h1); aL[3] = pk2(p6 - h2, p7 - h3);
            // PV for this 16-wide k-chunk
            #pragma unroll
            for (int nd = 0; nd < 8; ++nd) {
                int vb = (nd * 8 + gid) * VROW + (kc * 16 + 2 * tig) * 2;
                uint32_t bh0 = *(const uint32_t*)(smem + OFF_VHI + vb);
                uint32_t bh1 = *(const uint32_t*)(smem + OFF_VHI + vb + 16);
                uint32_t bl0 = *(const uint32_t*)(smem + OFF_VLO + vb);
                uint32_t bl1 = *(const uint32_t*)(smem + OFF_VLO + vb + 16);
                mma16816(o[nd], aH, bh0, bh1);
                mma16816(o[nd], aH, bl0, bl1);
                mma16816(o[nd], aL, bh0, bh1);
            }
            f0 = g0; f1 = g1; f2 = g2; f3 = g3;
        }
        __syncthreads();
    }

    // ---- write O ----
    {
        float* orow = out + ((long long)bh * Sc + qrow0) * Dc;
        #pragma unroll
        for (int nd = 0; nd < 8; ++nd) {
            int cc = nd * 8 + 2 * tig;
            *(float2*)(orow + cc)          = make_float2(o[nd][0], o[nd][1]);
            *(float2*)(orow + 8 * Dc + cc) = make_float2(o[nd][2], o[nd][3]);
        }
    }
}

// ---------------- launcher ----------------
extern "C" void kernel_launch(void* const* d_in, const int* in_sizes, int n_in,
                              void* d_out, int out_size) {
    const float* q = (const float*)d_in[0];
    const float* k = (const float*)d_in[1];
    const float* v = (const float*)d_in[2];
    const int*   m = (const int*)d_in[3];
    float* out  = (float*)d_out;
    float* attn = out + OUT_ELEMS;   // harness allocates output tuple (out, attn)

    cudaFuncSetAttribute(attn_main_kernel,
                         cudaFuncAttributeMaxDynamicSharedMemorySize, SMEM_BYTES);

    conv_qk_kernel<<<QKD / 256, 256>>>(q, k);
    conv_v_kernel<<<BHc * (Sc / 64), 256>>>(v);
    pack_mask_kernel<<<MASKW / 256, 256>>>(m);
    attn_main_kernel<<<dim3(NKT, BHc), 256, SMEM_BYTES>>>(out, attn);
}

// round 11
// speedup vs baseline: 1.7374x; 1.0303x over previous
#include <cuda_runtime.h>
#include <cuda_bf16.h>
#include <cstdint>

#define DEVINL __device__ __forceinline__

// ---------------- problem constants ----------------
constexpr int Sc = 2048, Dc = 64, BHc = 32;
constexpr int NKT = Sc / 128;                 // 16 k-tiles
constexpr int QKD = BHc * Sc * Dc;            // 4194304
constexpr int MASKW = Sc * Sc / 32;           // 131072
constexpr long long OUT_ELEMS  = (long long)QKD;
constexpr long long ATTN_ELEMS = (long long)BHc * Sc * Sc;

// ---------------- static device scratch ----------------
__device__ __nv_bfloat16 g_Qhi[QKD], g_Qlo[QKD], g_Khi[QKD], g_Klo[QKD];
__device__ __nv_bfloat16 g_Vthi[QKD], g_Vtlo[QKD];   // transposed: [bh][d][s]
__device__ unsigned g_maskbits[MASKW];

// ---------------- smem: double-buffered stages; K(ph1)/V(ph2) share --------
constexpr int KROW = 144;                    // 64 bf16 (128B) + 16B pad
constexpr int VROW = 272;                    // 128 bf16 (256B) + 16B pad
constexpr int OFF_KHI = 0;
constexpr int OFF_KLO = 128 * KROW;          // 18432
constexpr int OFF_VHI = 0;                   // reused in phase 2
constexpr int OFF_VLO = 64 * VROW;           // 17408
constexpr int STAGE   = 2 * 128 * KROW;      // 36864 (>= V region 34816)
constexpr int SMEM_BYTES = 2 * STAGE;        // 73728 (x2 CTAs = 147KB)

// ---------------- asm helpers ----------------
DEVINL void mma16816(float c[4], const uint32_t a[4], uint32_t b0, uint32_t b1) {
    asm volatile(
        "mma.sync.aligned.m16n8k16.row.col.f32.bf16.bf16.f32 "
        "{%0,%1,%2,%3}, {%4,%5,%6,%7}, {%8,%9}, {%0,%1,%2,%3};"
        : "+f"(c[0]), "+f"(c[1]), "+f"(c[2]), "+f"(c[3])
        : "r"(a[0]), "r"(a[1]), "r"(a[2]), "r"(a[3]), "r"(b0), "r"(b1));
}
DEVINL void ldsm_x4(uint32_t& r0, uint32_t& r1, uint32_t& r2, uint32_t& r3, uint32_t addr) {
    asm volatile("ldmatrix.sync.aligned.m8n8.x4.shared.b16 {%0,%1,%2,%3}, [%4];"
        : "=r"(r0), "=r"(r1), "=r"(r2), "=r"(r3) : "r"(addr));
}
DEVINL uint32_t pk2(float x, float y) {
    __nv_bfloat162 t = __floats2bfloat162_rn(x, y);
    return *(uint32_t*)&t;   // x in low half
}
DEVINL uint32_t smem_u32(const void* p) {
    uint32_t a;
    asm("{ .reg .u64 t; cvta.to.shared.u64 t, %1; cvt.u32.u64 %0, t; }" : "=r"(a) : "l"(p));
    return a;
}
DEVINL void cp_async16(uint32_t dst, const void* src) {
    asm volatile("cp.async.cg.shared.global [%0], [%1], 16;" :: "r"(dst), "l"(src));
}
#define CP_COMMIT()  asm volatile("cp.async.commit_group;" ::: "memory")
#define CP_WAIT(n)   asm volatile("cp.async.wait_group %0;" :: "n"(n) : "memory")

// ---------------- preprocessing ----------------
// q pre-scaled by 1/8 (=1/sqrt(64)) so the hot loop does exp(c) directly.
__global__ void conv_qk_kernel(const float* __restrict__ q, const float* __restrict__ k) {
    int i = blockIdx.x * 256 + threadIdx.x;
    float qv = q[i] * 0.125f;
    __nv_bfloat16 qh = __float2bfloat16(qv);
    g_Qhi[i] = qh;
    g_Qlo[i] = __float2bfloat16(qv - __bfloat162float(qh));
    float kv = k[i];
    __nv_bfloat16 kh = __float2bfloat16(kv);
    g_Khi[i] = kh;
    g_Klo[i] = __float2bfloat16(kv - __bfloat162float(kh));
}

// tiled transpose v[bh,s,d] -> g_Vt[bh,d,s] hi/lo
__global__ void conv_v_kernel(const float* __restrict__ v) {
    __shared__ float tile[64][65];
    int bh = blockIdx.x >> 5;
    int s0 = (blockIdx.x & 31) * 64;
    int tid = threadIdx.x;
    for (int i = tid; i < 64 * 64; i += 256) {
        int sr = i >> 6, dc = i & 63;
        tile[sr][dc] = v[((long long)bh * Sc + s0 + sr) * Dc + dc];
    }
    __syncthreads();
    for (int i = tid; i < 64 * 64; i += 256) {
        int dr = i >> 6, sc = i & 63;
        float vv = tile[sc][dr];
        __nv_bfloat16 vh = __float2bfloat16(vv);
        long long gi = ((long long)bh * Dc + dr) * Sc + s0 + sc;
        g_Vthi[gi] = vh;
        g_Vtlo[gi] = __float2bfloat16(vv - __bfloat162float(vh));
    }
}

__global__ void pack_mask_kernel(const int* __restrict__ m) {
    int i = blockIdx.x * 256 + threadIdx.x;     // row = i>>6, word = i&63
    int row = i >> 6, w = i & 63;
    const int4* p = (const int4*)(m + (long long)row * Sc + w * 32);
    unsigned bits = 0;
    #pragma unroll
    for (int g = 0; g < 8; ++g) {
        int4 x = p[g];
        bits |= (unsigned)(x.x != 0) << (g * 4 + 0);
        bits |= (unsigned)(x.y != 0) << (g * 4 + 1);
        bits |= (unsigned)(x.z != 0) << (g * 4 + 2);
        bits |= (unsigned)(x.w != 0) << (g * 4 + 3);
    }
    g_maskbits[i] = bits;
}

// ---------------- cp.async tile prefetchers ----------------
DEVINL void preload_k(uint32_t smb_stage, int bh, int kt, int tid) {
    const uint4* kh = (const uint4*)g_Khi + ((long long)bh * Sc + kt * 128) * 8;
    const uint4* kl = (const uint4*)g_Klo + ((long long)bh * Sc + kt * 128) * 8;
    #pragma unroll
    for (int i = tid; i < 128 * 8; i += 256) {
        int r = i >> 3, w = i & 7;
        uint32_t off = (uint32_t)(r * KROW + w * 16);
        cp_async16(smb_stage + OFF_KHI + off, kh + i);
        cp_async16(smb_stage + OFF_KLO + off, kl + i);
    }
}
DEVINL void preload_v(uint32_t smb_stage, int bh, int kt, int tid) {
    const uint4* vh = (const uint4*)g_Vthi;
    const uint4* vl = (const uint4*)g_Vtlo;
    #pragma unroll
    for (int i = tid; i < 64 * 16; i += 256) {
        int d = i >> 4, w = i & 15;
        uint32_t off = (uint32_t)(d * VROW + w * 16);
        long long gi = ((long long)bh * 64 + d) * 256 + kt * 16 + w;
        cp_async16(smb_stage + OFF_VHI + off, vh + gi);
        cp_async16(smb_stage + OFF_VLO + off, vl + gi);
    }
}

// ---------------- main fused kernel: two lean phases, LDSM + cp.async ------
__global__ void __launch_bounds__(256, 2)
attn_main_kernel(float* __restrict__ out, float* __restrict__ attn) {
    extern __shared__ __align__(16) char smem[];
    const int qt = blockIdx.x;             // 0..15
    const int bh = blockIdx.y;             // 0..31
    const int tid = threadIdx.x;
    const int wid = tid >> 5, lane = tid & 31;
    const int gid = lane >> 2, tig = lane & 3;
    const int r0 = wid * 16 + gid;         // q-row (block-local), second row r0+8
    const long long qrow0 = (long long)qt * 128 + r0;
    const uint32_t smb = smem_u32(smem);
    float* const abase = attn + ((long long)bh * Sc + qrow0) * Sc;

    // ldmatrix per-lane bases
    const uint32_t ldK_base = (uint32_t)((lane & 7) * KROW + (lane >> 3) * 16);
    const uint32_t ldV_base = (uint32_t)((lane & 7) * VROW + ((lane >> 3) & 1) * 16
                                         + (lane >> 4) * 8 * VROW);

    float lsum0 = 0.f, lsum1 = 0.f;

    // ================ PHASE 1: QK + exp -> attn (unnormalized) + lsum =======
    {
        preload_k(smb + 0 * STAGE, bh, 0, tid);
        CP_COMMIT();

        // stage Q tile into stage-1 K region (plain stores), pull A-frags
        {
            const uint4* qh = (const uint4*)g_Qhi + ((long long)bh * Sc + qt * 128) * 8;
            const uint4* ql = (const uint4*)g_Qlo + ((long long)bh * Sc + qt * 128) * 8;
            #pragma unroll
            for (int i = tid; i < 128 * 8; i += 256) {
                int r = i >> 3, w = i & 7;
                int off = STAGE + r * KROW + w * 16;
                *(uint4*)(smem + OFF_KHI + off) = qh[i];
                *(uint4*)(smem + OFF_KLO + off) = ql[i];
            }
        }
        __syncthreads();
        uint32_t qfh[4][4], qfl[4][4];
        #pragma unroll
        for (int kk = 0; kk < 4; ++kk) {
            int base = STAGE + r0 * KROW + (kk * 16 + 2 * tig) * 2;
            qfh[kk][0] = *(const uint32_t*)(smem + OFF_KHI + base);
            qfh[kk][1] = *(const uint32_t*)(smem + OFF_KHI + base + 8 * KROW);
            qfh[kk][2] = *(const uint32_t*)(smem + OFF_KHI + base + 16);
            qfh[kk][3] = *(const uint32_t*)(smem + OFF_KHI + base + 8 * KROW + 16);
            qfl[kk][0] = *(const uint32_t*)(smem + OFF_KLO + base);
            qfl[kk][1] = *(const uint32_t*)(smem + OFF_KLO + base + 8 * KROW);
            qfl[kk][2] = *(const uint32_t*)(smem + OFF_KLO + base + 16);
            qfl[kk][3] = *(const uint32_t*)(smem + OFF_KLO + base + 8 * KROW + 16);
        }
        __syncthreads();   // done reading Q before stage 1 is refilled

        const unsigned* mrow0 = g_maskbits + (long long)qrow0 * 64;
        const unsigned* mrow1 = mrow0 + 8 * 64;

        for (int kt = 0; kt < NKT; ++kt) {
            if (kt + 1 < NKT) {
                preload_k(smb + ((kt + 1) & 1) * STAGE, bh, kt + 1, tid);
                CP_COMMIT();
                CP_WAIT(1);
            } else {
                CP_WAIT(0);
            }
            __syncthreads();
            const uint32_t bufK = smb + (kt & 1) * STAGE;

            unsigned mw0[4], mw1[4];
            #pragma unroll
            for (int qd = 0; qd < 4; ++qd) { mw0[qd] = mrow0[kt * 4 + qd]; mw1[qd] = mrow1[kt * 4 + qd]; }
            float* arow0 = abase + kt * 128;

            #pragma unroll
            for (int nb = 0; nb < 16; ++nb) {
                uint32_t bH[8], bL[8];   // [kk*2 + half]
                uint32_t rowoff = (uint32_t)(nb * 8 * KROW) + ldK_base;
                ldsm_x4(bH[0], bH[1], bH[2], bH[3], bufK + OFF_KHI + rowoff);
                ldsm_x4(bH[4], bH[5], bH[6], bH[7], bufK + OFF_KHI + rowoff + 64);
                ldsm_x4(bL[0], bL[1], bL[2], bL[3], bufK + OFF_KLO + rowoff);
                ldsm_x4(bL[4], bL[5], bL[6], bL[7], bufK + OFF_KLO + rowoff + 64);
                float c1[4] = {0.f, 0.f, 0.f, 0.f};
                float c2[4] = {0.f, 0.f, 0.f, 0.f};
                #pragma unroll
                for (int kk = 0; kk < 4; ++kk) {
                    mma16816(c1, qfh[kk], bH[2 * kk], bH[2 * kk + 1]);
                    mma16816(c2, qfh[kk], bL[2 * kk], bL[2 * kk + 1]);
                    mma16816(c2, qfl[kk], bH[2 * kk], bH[2 * kk + 1]);
                }
                int bit = (nb & 3) * 8 + 2 * tig;
                unsigned w0 = mw0[nb >> 2], w1 = mw1[nb >> 2];
                float p0 = ((w0 >> bit) & 1u)       ? __expf(c1[0] + c2[0]) : 0.f;
                float p1 = ((w0 >> (bit + 1)) & 1u) ? __expf(c1[1] + c2[1]) : 0.f;
                float p2 = ((w1 >> bit) & 1u)       ? __expf(c1[2] + c2[2]) : 0.f;
                float p3 = ((w1 >> (bit + 1)) & 1u) ? __expf(c1[3] + c2[3]) : 0.f;
                lsum0 += p0 + p1;
                lsum1 += p2 + p3;
                int cc = nb * 8 + 2 * tig;
                *(float2*)(arow0 + cc)          = make_float2(p0, p1);
                *(float2*)(arow0 + 8 * Sc + cc) = make_float2(p2, p3);
            }
            __syncthreads();
        }
    }

    // ---- reduce row sums across quad, compute rinv ----
    lsum0 += __shfl_xor_sync(0xffffffffu, lsum0, 1);
    lsum0 += __shfl_xor_sync(0xffffffffu, lsum0, 2);
    lsum1 += __shfl_xor_sync(0xffffffffu, lsum1, 1);
    lsum1 += __shfl_xor_sync(0xffffffffu, lsum1, 2);
    const float rinv0 = (lsum0 > 0.f) ? 1.f / lsum0 : 0.f;
    const float rinv1 = (lsum1 > 0.f) ? 1.f / lsum1 : 0.f;

    __syncthreads();   // orders phase-1 global writes before phase-2 reads

    // ================ PHASE 2: read e, normalize+writeback, PV ==============
    float o[8][4];
    #pragma unroll
    for (int nd = 0; nd < 8; ++nd)
        #pragma unroll
        for (int j = 0; j < 4; ++j) o[nd][j] = 0.f;

    preload_v(smb + 0 * STAGE, bh, 0, tid);
    CP_COMMIT();

    for (int kt = 0; kt < NKT; ++kt) {
        if (kt + 1 < NKT) {
            preload_v(smb + ((kt + 1) & 1) * STAGE, bh, kt + 1, tid);
            CP_COMMIT();
            CP_WAIT(1);
        } else {
            CP_WAIT(0);
        }
        __syncthreads();
        const uint32_t bufV = smb + (kt & 1) * STAGE;
        float* arow0 = abase + kt * 128;

        // software pipeline: prefetch e-fragments one kc ahead
        float2 f0, f1, f2, f3;
        {
            int cc = 2 * tig;
            f0 = *(float2*)(arow0 + cc);
            f1 = *(float2*)(arow0 + 8 * Sc + cc);
            f2 = *(float2*)(arow0 + 8 + cc);
            f3 = *(float2*)(arow0 + 8 * Sc + 8 + cc);
        }
        #pragma unroll
        for (int kc = 0; kc < 8; ++kc) {
            float2 g0, g1, g2, g3;
            if (kc < 7) {
                int cc = (kc + 1) * 16 + 2 * tig;
                g0 = *(float2*)(arow0 + cc);
                g1 = *(float2*)(arow0 + 8 * Sc + cc);
                g2 = *(float2*)(arow0 + 8 + cc);
                g3 = *(float2*)(arow0 + 8 * Sc + 8 + cc);
            }
            float p0 = f0.x * rinv0, p1 = f0.y * rinv0;
            float p2 = f1.x * rinv1, p3 = f1.y * rinv1;
            float p4 = f2.x * rinv0, p5 = f2.y * rinv0;
            float p6 = f3.x * rinv1, p7 = f3.y * rinv1;
            {
                int cc = kc * 16 + 2 * tig;
                *(float2*)(arow0 + cc)              = make_float2(p0, p1);
                *(float2*)(arow0 + 8 * Sc + cc)     = make_float2(p2, p3);
                *(float2*)(arow0 + 8 + cc)          = make_float2(p4, p5);
                *(float2*)(arow0 + 8 * Sc + 8 + cc) = make_float2(p6, p7);
            }
            uint32_t aH[4], aL[4];
            float h0 = __bfloat162float(__float2bfloat16(p0));
            float h1 = __bfloat162float(__float2bfloat16(p1));
            float h2 = __bfloat162float(__float2bfloat16(p2));
            float h3 = __bfloat162float(__float2bfloat16(p3));
            aH[0] = pk2(h0, h1); aH[1] = pk2(h2, h3);
            aL[0] = pk2(p0 - h0, p1 - h1); aL[1] = pk2(p2 - h2, p3 - h3);
            h0 = __bfloat162float(__float2bfloat16(p4));
            h1 = __bfloat162float(__float2bfloat16(p5));
            h2 = __bfloat162float(__float2bfloat16(p6));
            h3 = __bfloat162float(__float2bfloat16(p7));
            aH[2] = pk2(h0, h1); aH[3] = pk2(h2, h3);
            aL[2] = pk2(p4 - h0, p5 - h1); aL[3] = pk2(p6 - h2, p7 - h3);

            // PV for this 16-wide k-chunk, V frags via ldmatrix (nd pairs)
            #pragma unroll
            for (int p = 0; p < 4; ++p) {
                uint32_t addr = bufV + (uint32_t)(p * 16 * VROW + kc * 32) + ldV_base;
                uint32_t vh0, vh1, vh2, vh3, vl0, vl1, vl2, vl3;
                ldsm_x4(vh0, vh1, vh2, vh3, addr + OFF_VHI);
                ldsm_x4(vl0, vl1, vl2, vl3, addr + OFF_VLO);
                mma16816(o[2 * p],     aH, vh0, vh1);
                mma16816(o[2 * p],     aH, vl0, vl1);
                mma16816(o[2 * p],     aL, vh0, vh1);
                mma16816(o[2 * p + 1], aH, vh2, vh3);
                mma16816(o[2 * p + 1], aH, vl2, vl3);
                mma16816(o[2 * p + 1], aL, vh2, vh3);
            }
            f0 = g0; f1 = g1; f2 = g2; f3 = g3;
        }
        __syncthreads();
    }

    // ---- write O ----
    {
        float* orow = out + ((long long)bh * Sc + qrow0) * Dc;
        #pragma unroll
        for (int nd = 0; nd < 8; ++nd) {
            int cc = nd * 8 + 2 * tig;
            *(float2*)(orow + cc)          = make_float2(o[nd][0], o[nd][1]);
            *(float2*)(orow + 8 * Dc + cc) = make_float2(o[nd][2], o[nd][3]);
        }
    }
}

// ---------------- launcher ----------------
extern "C" void kernel_launch(void* const* d_in, const int* in_sizes, int n_in,
                              void* d_out, int out_size) {
    const float* q = (const float*)d_in[0];
    const float* k = (const float*)d_in[1];
    const float* v = (const float*)d_in[2];
    const int*   m = (const int*)d_in[3];
    float* out  = (float*)d_out;
    float* attn = out + OUT_ELEMS;

    cudaFuncSetAttribute(attn_main_kernel,
                         cudaFuncAttributeMaxDynamicSharedMemorySize, SMEM_BYTES);

    conv_qk_kernel<<<QKD / 256, 256>>>(q, k);
    conv_v_kernel<<<BHc * (Sc / 64), 256>>>(v);
    pack_mask_kernel<<<MASKW / 256, 256>>>(m);
    attn_main_kernel<<<dim3(NKT, BHc), 256, SMEM_BYTES>>>(out, attn);
}

// round 15
// speedup vs baseline: 1.7543x; 1.0098x over previous
#include <cuda_runtime.h>
#include <cuda_bf16.h>
#include <cstdint>

#define DEVINL __device__ __forceinline__

// ---------------- problem constants ----------------
constexpr int Sc = 2048, Dc = 64, BHc = 32;
constexpr int NKT = Sc / 128;                 // 16 k-tiles
constexpr int QKD = BHc * Sc * Dc;            // 4194304
constexpr int MASKW = Sc * Sc / 32;           // 131072
constexpr long long OUT_ELEMS  = (long long)QKD;
constexpr long long ATTN_ELEMS = (long long)BHc * Sc * Sc;

// ---------------- static device scratch ----------------
__device__ __nv_bfloat16 g_Qhi[QKD], g_Qlo[QKD], g_Khi[QKD], g_Klo[QKD];
__device__ __nv_bfloat16 g_Vthi[QKD], g_Vtlo[QKD];   // transposed: [bh][d][s]
__device__ unsigned g_maskbits[MASKW];

// ---------------- smem: double-buffered stages; K(ph1)/V(ph2) share --------
constexpr int KROW = 144;                    // 64 bf16 (128B) + 16B pad
constexpr int VROW = 272;                    // 128 bf16 (256B) + 16B pad
constexpr int OFF_KHI = 0;
constexpr int OFF_KLO = 128 * KROW;          // 18432
constexpr int OFF_VHI = 0;                   // reused in phase 2
constexpr int OFF_VLO = 64 * VROW;           // 17408
constexpr int STAGE   = 2 * 128 * KROW;      // 36864 (>= V region 34816)
constexpr int OFF_LS  = 2 * STAGE;           // 2 x 128 floats (lsum halves)
constexpr int OFF_RV  = OFF_LS + 1024;       // 128 floats (rinv)
constexpr int SMEM_BYTES = OFF_RV + 512;     // 75264 (x2 CTAs = 150.5KB)

// ---------------- asm helpers ----------------
DEVINL void mma16816(float c[4], const uint32_t a[4], uint32_t b0, uint32_t b1) {
    asm volatile(
        "mma.sync.aligned.m16n8k16.row.col.f32.bf16.bf16.f32 "
        "{%0,%1,%2,%3}, {%4,%5,%6,%7}, {%8,%9}, {%0,%1,%2,%3};"
        : "+f"(c[0]), "+f"(c[1]), "+f"(c[2]), "+f"(c[3])
        : "r"(a[0]), "r"(a[1]), "r"(a[2]), "r"(a[3]), "r"(b0), "r"(b1));
}
DEVINL void ldsm_x4(uint32_t& r0, uint32_t& r1, uint32_t& r2, uint32_t& r3, uint32_t addr) {
    asm volatile("ldmatrix.sync.aligned.m8n8.x4.shared.b16 {%0,%1,%2,%3}, [%4];"
        : "=r"(r0), "=r"(r1), "=r"(r2), "=r"(r3) : "r"(addr));
}
DEVINL uint32_t pk2(float x, float y) {
    __nv_bfloat162 t = __floats2bfloat162_rn(x, y);
    return *(uint32_t*)&t;   // x in low half
}
DEVINL uint32_t smem_u32(const void* p) {
    uint32_t a;
    asm("{ .reg .u64 t; cvta.to.shared.u64 t, %1; cvt.u32.u64 %0, t; }" : "=r"(a) : "l"(p));
    return a;
}
DEVINL void cp_async16(uint32_t dst, const void* src) {
    asm volatile("cp.async.cg.shared.global [%0], [%1], 16;" :: "r"(dst), "l"(src));
}
#define CP_COMMIT()  asm volatile("cp.async.commit_group;" ::: "memory")
#define CP_WAIT(n)   asm volatile("cp.async.wait_group %0;" :: "n"(n) : "memory")

// ---------------- preprocessing ----------------
// q pre-scaled by 1/8 (=1/sqrt(64)) so the hot loop does exp(c) directly.
__global__ void conv_qk_kernel(const float* __restrict__ q, const float* __restrict__ k) {
    int i = blockIdx.x * 256 + threadIdx.x;
    float qv = q[i] * 0.125f;
    __nv_bfloat16 qh = __float2bfloat16(qv);
    g_Qhi[i] = qh;
    g_Qlo[i] = __float2bfloat16(qv - __bfloat162float(qh));
    float kv = k[i];
    __nv_bfloat16 kh = __float2bfloat16(kv);
    g_Khi[i] = kh;
    g_Klo[i] = __float2bfloat16(kv - __bfloat162float(kh));
}

// tiled transpose v[bh,s,d] -> g_Vt[bh,d,s] hi/lo
__global__ void conv_v_kernel(const float* __restrict__ v) {
    __shared__ float tile[64][65];
    int bh = blockIdx.x >> 5;
    int s0 = (blockIdx.x & 31) * 64;
    int tid = threadIdx.x;
    for (int i = tid; i < 64 * 64; i += 256) {
        int sr = i >> 6, dc = i & 63;
        tile[sr][dc] = v[((long long)bh * Sc + s0 + sr) * Dc + dc];
    }
    __syncthreads();
    for (int i = tid; i < 64 * 64; i += 256) {
        int dr = i >> 6, sc = i & 63;
        float vv = tile[sc][dr];
        __nv_bfloat16 vh = __float2bfloat16(vv);
        long long gi = ((long long)bh * Dc + dr) * Sc + s0 + sc;
        g_Vthi[gi] = vh;
        g_Vtlo[gi] = __float2bfloat16(vv - __bfloat162float(vh));
    }
}

__global__ void pack_mask_kernel(const int* __restrict__ m) {
    int i = blockIdx.x * 256 + threadIdx.x;     // row = i>>6, word = i&63
    int row = i >> 6, w = i & 63;
    const int4* p = (const int4*)(m + (long long)row * Sc + w * 32);
    unsigned bits = 0;
    #pragma unroll
    for (int g = 0; g < 8; ++g) {
        int4 x = p[g];
        bits |= (unsigned)(x.x != 0) << (g * 4 + 0);
        bits |= (unsigned)(x.y != 0) << (g * 4 + 1);
        bits |= (unsigned)(x.z != 0) << (g * 4 + 2);
        bits |= (unsigned)(x.w != 0) << (g * 4 + 3);
    }
    g_maskbits[i] = bits;
}

// ---------------- cp.async tile prefetchers ----------------
DEVINL void preload_k(uint32_t smb_stage, int bh, int kt, int tid) {
    const uint4* kh = (const uint4*)g_Khi + ((long long)bh * Sc + kt * 128) * 8;
    const uint4* kl = (const uint4*)g_Klo + ((long long)bh * Sc + kt * 128) * 8;
    #pragma unroll
    for (int i = tid; i < 128 * 8; i += 256) {
        int r = i >> 3, w = i & 7;
        uint32_t off = (uint32_t)(r * KROW + w * 16);
        cp_async16(smb_stage + OFF_KHI + off, kh + i);
        cp_async16(smb_stage + OFF_KLO + off, kl + i);
    }
}
DEVINL void preload_v(uint32_t smb_stage, int bh, int kt, int tid) {
    const uint4* vh = (const uint4*)g_Vthi;
    const uint4* vl = (const uint4*)g_Vtlo;
    #pragma unroll
    for (int i = tid; i < 64 * 16; i += 256) {
        int d = i >> 4, w = i & 15;
        uint32_t off = (uint32_t)(d * VROW + w * 16);
        long long gi = ((long long)bh * 64 + d) * 256 + kt * 16 + w;
        cp_async16(smb_stage + OFF_VHI + off, vh + gi);
        cp_async16(smb_stage + OFF_VLO + off, vl + gi);
    }
}

// ---------------- main fused kernel ----------------
__global__ void __launch_bounds__(256, 2)
attn_main_kernel(float* __restrict__ out, float* __restrict__ attn) {
    extern __shared__ __align__(16) char smem[];
    const int qt = blockIdx.x;             // 0..15
    const int bh = blockIdx.y;             // 0..31
    const int tid = threadIdx.x;
    const int wid = tid >> 5, lane = tid & 31;
    const int gid = lane >> 2, tig = lane & 3;
    const uint32_t smb = smem_u32(smem);

    // ldmatrix per-lane bases
    const uint32_t ldK_base = (uint32_t)((lane & 7) * KROW + (lane >> 3) * 16);
    const uint32_t ldV_base = (uint32_t)((lane & 7) * VROW + ((lane >> 3) & 1) * 16
                                         + (lane >> 4) * 8 * VROW);

    // ================ PHASE 1: QK + exp -> attn (unnormalized) + lsum =======
    // warp tile M=32 x N=64:  mg = wid&3 (rows mg*32..+31), ng = wid>>2 (cols ng*64..+63)
    {
        const int mg = wid & 3, ng = wid >> 2;
        const int r0a = mg * 32 + gid;             // frag rows r0a, r0a+8; second frag +16,+24
        const int ncol0 = ng * 64;

        preload_k(smb + 0 * STAGE, bh, 0, tid);
        CP_COMMIT();

        // stage Q tile into stage-1 region (plain stores), pull A-frags
        {
            const uint4* qh = (const uint4*)g_Qhi + ((long long)bh * Sc + qt * 128) * 8;
            const uint4* ql = (const uint4*)g_Qlo + ((long long)bh * Sc + qt * 128) * 8;
            #pragma unroll
            for (int i = tid; i < 128 * 8; i += 256) {
                int r = i >> 3, w = i & 7;
                int off = STAGE + r * KROW + w * 16;
                *(uint4*)(smem + OFF_KHI + off) = qh[i];
                *(uint4*)(smem + OFF_KLO + off) = ql[i];
            }
        }
        __syncthreads();
        uint32_t qfh[4][2][4], qfl[4][2][4];
        #pragma unroll
        for (int kk = 0; kk < 4; ++kk)
            #pragma unroll
            for (int m = 0; m < 2; ++m) {
                int base = STAGE + (r0a + m * 16) * KROW + (kk * 16 + 2 * tig) * 2;
                qfh[kk][m][0] = *(const uint32_t*)(smem + OFF_KHI + base);
                qfh[kk][m][1] = *(const uint32_t*)(smem + OFF_KHI + base + 8 * KROW);
                qfh[kk][m][2] = *(const uint32_t*)(smem + OFF_KHI + base + 16);
                qfh[kk][m][3] = *(const uint32_t*)(smem + OFF_KHI + base + 8 * KROW + 16);
                qfl[kk][m][0] = *(const uint32_t*)(smem + OFF_KLO + base);
                qfl[kk][m][1] = *(const uint32_t*)(smem + OFF_KLO + base + 8 * KROW);
                qfl[kk][m][2] = *(const uint32_t*)(smem + OFF_KLO + base + 16);
                qfl[kk][m][3] = *(const uint32_t*)(smem + OFF_KLO + base + 8 * KROW + 16);
            }
        __syncthreads();   // done reading Q before stage 1 is refilled

        const unsigned* mr0 = g_maskbits + (long long)(qt * 128 + r0a) * 64;
        const unsigned* mr1 = mr0 + 8 * 64;
        const unsigned* mr2 = mr0 + 16 * 64;
        const unsigned* mr3 = mr0 + 24 * 64;
        float ls0 = 0.f, ls1 = 0.f, ls2 = 0.f, ls3 = 0.f;
        float* const ab = attn + ((long long)bh * Sc + qt * 128 + r0a) * Sc;

        for (int kt = 0; kt < NKT; ++kt) {
            CP_WAIT(0);
            __syncthreads();                        // tile kt ready; other buf free
            if (kt + 1 < NKT) {
                preload_k(smb + ((kt + 1) & 1) * STAGE, bh, kt + 1, tid);
                CP_COMMIT();
            }
            const uint32_t bufK = smb + (kt & 1) * STAGE;
            const int wi = kt * 4 + ng * 2;
            unsigned mwa[2] = { mr0[wi], mr0[wi + 1] };
            unsigned mwb[2] = { mr1[wi], mr1[wi + 1] };
            unsigned mwc[2] = { mr2[wi], mr2[wi + 1] };
            unsigned mwd[2] = { mr3[wi], mr3[wi + 1] };
            float* arow = ab + kt * 128 + ncol0;

            #pragma unroll
            for (int nb = 0; nb < 8; ++nb) {
                uint32_t bH[8], bL[8];
                uint32_t rowoff = (uint32_t)((ncol0 + nb * 8) * KROW) + ldK_base;
                ldsm_x4(bH[0], bH[1], bH[2], bH[3], bufK + OFF_KHI + rowoff);
                ldsm_x4(bH[4], bH[5], bH[6], bH[7], bufK + OFF_KHI + rowoff + 64);
                ldsm_x4(bL[0], bL[1], bL[2], bL[3], bufK + OFF_KLO + rowoff);
                ldsm_x4(bL[4], bL[5], bL[6], bL[7], bufK + OFF_KLO + rowoff + 64);
                float cA1[4] = {0.f,0.f,0.f,0.f}, cA2[4] = {0.f,0.f,0.f,0.f};
                float cB1[4] = {0.f,0.f,0.f,0.f}, cB2[4] = {0.f,0.f,0.f,0.f};
                #pragma unroll
                for (int kk = 0; kk < 4; ++kk) {
                    uint32_t b0 = bH[2 * kk], b1 = bH[2 * kk + 1];
                    uint32_t l0 = bL[2 * kk], l1 = bL[2 * kk + 1];
                    mma16816(cA1, qfh[kk][0], b0, b1);
                    mma16816(cB1, qfh[kk][1], b0, b1);
                    mma16816(cA2, qfh[kk][0], l0, l1);
                    mma16816(cA2, qfl[kk][0], b0, b1);
                    mma16816(cB2, qfh[kk][1], l0, l1);
                    mma16816(cB2, qfl[kk][1], b0, b1);
                }
                int bit = (nb & 3) * 8 + 2 * tig;
                unsigned wa = mwa[nb >> 2], wb = mwb[nb >> 2];
                unsigned wc = mwc[nb >> 2], wd = mwd[nb >> 2];
                float pa0 = ((wa >> bit) & 1u)       ? __expf(cA1[0] + cA2[0]) : 0.f;
                float pa1 = ((wa >> (bit + 1)) & 1u) ? __expf(cA1[1] + cA2[1]) : 0.f;
                float pb0 = ((wb >> bit) & 1u)       ? __expf(cA1[2] + cA2[2]) : 0.f;
                float pb1 = ((wb >> (bit + 1)) & 1u) ? __expf(cA1[3] + cA2[3]) : 0.f;
                float pc0 = ((wc >> bit) & 1u)       ? __expf(cB1[0] + cB2[0]) : 0.f;
                float pc1 = ((wc >> (bit + 1)) & 1u) ? __expf(cB1[1] + cB2[1]) : 0.f;
                float pd0 = ((wd >> bit) & 1u)       ? __expf(cB1[2] + cB2[2]) : 0.f;
                float pd1 = ((wd >> (bit + 1)) & 1u) ? __expf(cB1[3] + cB2[3]) : 0.f;
                ls0 += pa0 + pa1;  ls1 += pb0 + pb1;
                ls2 += pc0 + pc1;  ls3 += pd0 + pd1;
                int cc = nb * 8 + 2 * tig;
                *(float2*)(arow + cc)           = make_float2(pa0, pa1);
                *(float2*)(arow + 8 * Sc + cc)  = make_float2(pb0, pb1);
                *(float2*)(arow + 16 * Sc + cc) = make_float2(pc0, pc1);
                *(float2*)(arow + 24 * Sc + cc) = make_float2(pd0, pd1);
            }
        }

        // overlap first V prefetch with the reduction
        preload_v(smb + 0 * STAGE, bh, 0, tid);
        CP_COMMIT();

        // quad-reduce and publish partial sums
        ls0 += __shfl_xor_sync(0xffffffffu, ls0, 1);
        ls0 += __shfl_xor_sync(0xffffffffu, ls0, 2);
        ls1 += __shfl_xor_sync(0xffffffffu, ls1, 1);
        ls1 += __shfl_xor_sync(0xffffffffu, ls1, 2);
        ls2 += __shfl_xor_sync(0xffffffffu, ls2, 1);
        ls2 += __shfl_xor_sync(0xffffffffu, ls2, 2);
        ls3 += __shfl_xor_sync(0xffffffffu, ls3, 1);
        ls3 += __shfl_xor_sync(0xffffffffu, ls3, 2);
        float* lsArr = (float*)(smem + OFF_LS);
        if (tig == 0) {
            lsArr[ng * 128 + r0a]      = ls0;
            lsArr[ng * 128 + r0a + 8]  = ls1;
            lsArr[ng * 128 + r0a + 16] = ls2;
            lsArr[ng * 128 + r0a + 24] = ls3;
        }
        __syncthreads();
        if (tid < 128) {
            float l = lsArr[tid] + lsArr[128 + tid];
            ((float*)(smem + OFF_RV))[tid] = (l > 0.f) ? 1.f / l : 0.f;
        }
        __syncthreads();
    }

    // ================ PHASE 2: read e, normalize+writeback, PV ==============
    const int r0 = wid * 16 + gid;
    const long long qrow0 = (long long)qt * 128 + r0;
    const float rinv0 = ((const float*)(smem + OFF_RV))[r0];
    const float rinv1 = ((const float*)(smem + OFF_RV))[r0 + 8];
    float* const abase = attn + ((long long)bh * Sc + qrow0) * Sc;

    float o[8][4];
    #pragma unroll
    for (int nd = 0; nd < 8; ++nd)
        #pragma unroll
        for (int j = 0; j < 4; ++j) o[nd][j] = 0.f;

    for (int kt = 0; kt < NKT; ++kt) {
        CP_WAIT(0);
        __syncthreads();
        if (kt + 1 < NKT) {
            preload_v(smb + ((kt + 1) & 1) * STAGE, bh, kt + 1, tid);
            CP_COMMIT();
        }
        const uint32_t bufV = smb + (kt & 1) * STAGE;
        float* arow0 = abase + kt * 128;

        float2 f0, f1, f2, f3;
        {
            int cc = 2 * tig;
            f0 = *(float2*)(arow0 + cc);
            f1 = *(float2*)(arow0 + 8 * Sc + cc);
            f2 = *(float2*)(arow0 + 8 + cc);
            f3 = *(float2*)(arow0 + 8 * Sc + 8 + cc);
        }
        #pragma unroll
        for (int kc = 0; kc < 8; ++kc) {
            float2 g0, g1, g2, g3;
            if (kc < 7) {
                int cc = (kc + 1) * 16 + 2 * tig;
                g0 = *(float2*)(arow0 + cc);
                g1 = *(float2*)(arow0 + 8 * Sc + cc);
                g2 = *(float2*)(arow0 + 8 + cc);
                g3 = *(float2*)(arow0 + 8 * Sc + 8 + cc);
            }
            float p0 = f0.x * rinv0, p1 = f0.y * rinv0;
            float p2 = f1.x * rinv1, p3 = f1.y * rinv1;
            float p4 = f2.x * rinv0, p5 = f2.y * rinv0;
            float p6 = f3.x * rinv1, p7 = f3.y * rinv1;
            {
                int cc = kc * 16 + 2 * tig;
                *(float2*)(arow0 + cc)              = make_float2(p0, p1);
                *(float2*)(arow0 + 8 * Sc + cc)     = make_float2(p2, p3);
                *(float2*)(arow0 + 8 + cc)          = make_float2(p4, p5);
                *(float2*)(arow0 + 8 * Sc + 8 + cc) = make_float2(p6, p7);
            }
            uint32_t aH[4], aL[4];
            float h0 = __bfloat162float(__float2bfloat16(p0));
            float h1 = __bfloat162float(__float2bfloat16(p1));
            float h2 = __bfloat162float(__float2bfloat16(p2));
            float h3 = __bfloat162float(__float2bfloat16(p3));
            aH[0] = pk2(h0, h1); aH[1] = pk2(h2, h3);
            aL[0] = pk2(p0 - h0, p1 - h1); aL[1] = pk2(p2 - h2, p3 - h3);
            h0 = __bfloat162float(__float2bfloat16(p4));
            h1 = __bfloat162float(__float2bfloat16(p5));
            h2 = __bfloat162float(__float2bfloat16(p6));
            h3 = __bfloat162float(__float2bfloat16(p7));
            aH[2] = pk2(h0, h1); aH[3] = pk2(h2, h3);
            aL[2] = pk2(p4 - h0, p5 - h1); aL[3] = pk2(p6 - h2, p7 - h3);

            #pragma unroll
            for (int p = 0; p < 4; ++p) {
                uint32_t addr = bufV + (uint32_t)(p * 16 * VROW + kc * 32) + ldV_base;
                uint32_t vh0, vh1, vh2, vh3, vl0, vl1, vl2, vl3;
                ldsm_x4(vh0, vh1, vh2, vh3, addr + OFF_VHI);
                ldsm_x4(vl0, vl1, vl2, vl3, addr + OFF_VLO);
                mma16816(o[2 * p],     aH, vh0, vh1);
                mma16816(o[2 * p],     aH, vl0, vl1);
                mma16816(o[2 * p],     aL, vh0, vh1);
                mma16816(o[2 * p + 1], aH, vh2, vh3);
                mma16816(o[2 * p + 1], aH, vl2, vl3);
                mma16816(o[2 * p + 1], aL, vh2, vh3);
            }
            f0 = g0; f1 = g1; f2 = g2; f3 = g3;
        }
    }

    // ---- write O ----
    {
        float* orow = out + ((long long)bh * Sc + qrow0) * Dc;
        #pragma unroll
        for (int nd = 0; nd < 8; ++nd) {
            int cc = nd * 8 + 2 * tig;
            *(float2*)(orow + cc)          = make_float2(o[nd][0], o[nd][1]);
            *(float2*)(orow + 8 * Dc + cc) = make_float2(o[nd][2], o[nd][3]);
        }
    }
}

// ---------------- launcher ----------------
extern "C" void kernel_launch(void* const* d_in, const int* in_sizes, int n_in,
                              void* d_out, int out_size) {
    const float* q = (const float*)d_in[0];
    const float* k = (const float*)d_in[1];
    const float* v = (const float*)d_in[2];
    const int*   m = (const int*)d_in[3];
    float* out  = (float*)d_out;
    float* attn = out + OUT_ELEMS;

    cudaFuncSetAttribute(attn_main_kernel,
                         cudaFuncAttributeMaxDynamicSharedMemorySize, SMEM_BYTES);

    conv_qk_kernel<<<QKD / 256, 256>>>(q, k);
    conv_v_kernel<<<BHc * (Sc / 64), 256>>>(v);
    pack_mask_kernel<<<MASKW / 256, 256>>>(m);
    attn_main_kernel<<<dim3(NKT, BHc), 256, SMEM_BYTES>>>(out, attn);
}

// round 17
// speedup vs baseline: 1.8933x; 1.0792x over previous
#include <cuda_runtime.h>
#include <cuda_bf16.h>
#include <cstdint>

#define DEVINL __device__ __forceinline__

// ---------------- problem constants ----------------
constexpr int Sc = 2048, Dc = 64, BHc = 32;
constexpr int NKT = Sc / 128;                 // 16 k-tiles
constexpr int QKD = BHc * Sc * Dc;            // 4194304
constexpr int MASKW = Sc * Sc / 32;           // 131072
constexpr long long OUT_ELEMS  = (long long)QKD;
constexpr long long ATTN_ELEMS = (long long)BHc * Sc * Sc;

// ---------------- static device scratch ----------------
__device__ __nv_bfloat16 g_Qhi[QKD], g_Qlo[QKD], g_Khi[QKD], g_Klo[QKD];
__device__ __nv_bfloat16 g_Vthi[QKD], g_Vtlo[QKD];   // transposed: [bh][d][s]
__device__ unsigned g_maskbits[MASKW];

// ---------------- smem: double-buffered stages; K(ph1)/V(ph2) share --------
constexpr int KROW = 144;                    // 64 bf16 (128B) + 16B pad
constexpr int VROW = 272;                    // 128 bf16 (256B) + 16B pad
constexpr int OFF_KHI = 0;
constexpr int OFF_KLO = 128 * KROW;          // 18432
constexpr int OFF_VHI = 0;                   // reused in phase 2
constexpr int OFF_VLO = 64 * VROW;           // 17408
constexpr int STAGE   = 2 * 128 * KROW;      // 36864 (>= V region 34816)
constexpr int OFF_LS  = 2 * STAGE;           // 2 x 128 floats (lsum halves)
constexpr int OFF_RV  = OFF_LS + 1024;       // 128 floats (rinv)
constexpr int SMEM_BYTES = OFF_RV + 512;     // 75264 (x2 CTAs = 150.5KB)

// ---------------- asm helpers ----------------
DEVINL void mma16816(float c[4], const uint32_t a[4], uint32_t b0, uint32_t b1) {
    asm volatile(
        "mma.sync.aligned.m16n8k16.row.col.f32.bf16.bf16.f32 "
        "{%0,%1,%2,%3}, {%4,%5,%6,%7}, {%8,%9}, {%0,%1,%2,%3};"
        : "+f"(c[0]), "+f"(c[1]), "+f"(c[2]), "+f"(c[3])
        : "r"(a[0]), "r"(a[1]), "r"(a[2]), "r"(a[3]), "r"(b0), "r"(b1));
}
DEVINL void ldsm_x4(uint32_t& r0, uint32_t& r1, uint32_t& r2, uint32_t& r3, uint32_t addr) {
    asm volatile("ldmatrix.sync.aligned.m8n8.x4.shared.b16 {%0,%1,%2,%3}, [%4];"
        : "=r"(r0), "=r"(r1), "=r"(r2), "=r"(r3) : "r"(addr));
}
DEVINL uint32_t pk2(float x, float y) {
    __nv_bfloat162 t = __floats2bfloat162_rn(x, y);
    return *(uint32_t*)&t;   // x in low half
}
DEVINL uint32_t smem_u32(const void* p) {
    uint32_t a;
    asm("{ .reg .u64 t; cvta.to.shared.u64 t, %1; cvt.u32.u64 %0, t; }" : "=r"(a) : "l"(p));
    return a;
}
DEVINL void cp_async16(uint32_t dst, const void* src) {
    asm volatile("cp.async.cg.shared.global [%0], [%1], 16;" :: "r"(dst), "l"(src));
}
#define CP_COMMIT()  asm volatile("cp.async.commit_group;" ::: "memory")
#define CP_WAIT(n)   asm volatile("cp.async.wait_group %0;" :: "n"(n) : "memory")

// ---------------- preprocessing ----------------
// q pre-scaled by 1/8 (=1/sqrt(64)) so the hot loop does exp(c) directly.
__global__ void conv_qk_kernel(const float* __restrict__ q, const float* __restrict__ k) {
    int i = blockIdx.x * 256 + threadIdx.x;
    float qv = q[i] * 0.125f;
    __nv_bfloat16 qh = __float2bfloat16(qv);
    g_Qhi[i] = qh;
    g_Qlo[i] = __float2bfloat16(qv - __bfloat162float(qh));
    float kv = k[i];
    __nv_bfloat16 kh = __float2bfloat16(kv);
    g_Khi[i] = kh;
    g_Klo[i] = __float2bfloat16(kv - __bfloat162float(kh));
}

// tiled transpose v[bh,s,d] -> g_Vt[bh,d,s] hi/lo
__global__ void conv_v_kernel(const float* __restrict__ v) {
    __shared__ float tile[64][65];
    int bh = blockIdx.x >> 5;
    int s0 = (blockIdx.x & 31) * 64;
    int tid = threadIdx.x;
    for (int i = tid; i < 64 * 64; i += 256) {
        int sr = i >> 6, dc = i & 63;
        tile[sr][dc] = v[((long long)bh * Sc + s0 + sr) * Dc + dc];
    }
    __syncthreads();
    for (int i = tid; i < 64 * 64; i += 256) {
        int dr = i >> 6, sc = i & 63;
        float vv = tile[sc][dr];
        __nv_bfloat16 vh = __float2bfloat16(vv);
        long long gi = ((long long)bh * Dc + dr) * Sc + s0 + sc;
        g_Vthi[gi] = vh;
        g_Vtlo[gi] = __float2bfloat16(vv - __bfloat162float(vh));
    }
}

__global__ void pack_mask_kernel(const int* __restrict__ m) {
    int i = blockIdx.x * 256 + threadIdx.x;     // row = i>>6, word = i&63
    int row = i >> 6, w = i & 63;
    const int4* p = (const int4*)(m + (long long)row * Sc + w * 32);
    unsigned bits = 0;
    #pragma unroll
    for (int g = 0; g < 8; ++g) {
        int4 x = p[g];
        bits |= (unsigned)(x.x != 0) << (g * 4 + 0);
        bits |= (unsigned)(x.y != 0) << (g * 4 + 1);
        bits |= (unsigned)(x.z != 0) << (g * 4 + 2);
        bits |= (unsigned)(x.w != 0) << (g * 4 + 3);
    }
    g_maskbits[i] = bits;
}

// ---------------- cp.async tile prefetchers ----------------
DEVINL void preload_k(uint32_t smb_stage, int bh, int kt, int tid) {
    const uint4* kh = (const uint4*)g_Khi + ((long long)bh * Sc + kt * 128) * 8;
    const uint4* kl = (const uint4*)g_Klo + ((long long)bh * Sc + kt * 128) * 8;
    #pragma unroll
    for (int i = tid; i < 128 * 8; i += 256) {
        int r = i >> 3, w = i & 7;
        uint32_t off = (uint32_t)(r * KROW + w * 16);
        cp_async16(smb_stage + OFF_KHI + off, kh + i);
        cp_async16(smb_stage + OFF_KLO + off, kl + i);
    }
}
DEVINL void preload_v(uint32_t smb_stage, int bh, int kt, int tid) {
    const uint4* vh = (const uint4*)g_Vthi;
    const uint4* vl = (const uint4*)g_Vtlo;
    #pragma unroll
    for (int i = tid; i < 64 * 16; i += 256) {
        int d = i >> 4, w = i & 15;
        uint32_t off = (uint32_t)(d * VROW + w * 16);
        long long gi = ((long long)bh * 64 + d) * 256 + kt * 16 + w;
        cp_async16(smb_stage + OFF_VHI + off, vh + gi);
        cp_async16(smb_stage + OFF_VLO + off, vl + gi);
    }
}

// ---------------- main fused kernel ----------------
__global__ void __launch_bounds__(256, 2)
attn_main_kernel(float* __restrict__ out, float* __restrict__ attn) {
    extern __shared__ __align__(16) char smem[];
    const int qt = blockIdx.x;             // 0..15
    const int bh = blockIdx.y;             // 0..31
    const int tid = threadIdx.x;
    const int wid = tid >> 5, lane = tid & 31;
    const int gid = lane >> 2, tig = lane & 3;
    const uint32_t smb = smem_u32(smem);

    // ldmatrix per-lane bases
    const uint32_t ldK_base = (uint32_t)((lane & 7) * KROW + (lane >> 3) * 16);
    const uint32_t ldV_base = (uint32_t)((lane & 7) * VROW + ((lane >> 3) & 1) * 16
                                         + (lane >> 4) * 8 * VROW);

    // ================ PHASE 1: QK + exp -> attn (unnormalized) + lsum =======
    // warp tile M=32 x N=64:  mg = wid&3 (rows mg*32..+31), ng = wid>>2 (cols ng*64..+63)
    {
        const int mg = wid & 3, ng = wid >> 2;
        const int r0a = mg * 32 + gid;             // frag rows r0a, r0a+8; second frag +16,+24
        const int ncol0 = ng * 64;

        preload_k(smb + 0 * STAGE, bh, 0, tid);
        CP_COMMIT();

        // stage Q tile into stage-1 region (plain stores), pull A-frags
        {
            const uint4* qh = (const uint4*)g_Qhi + ((long long)bh * Sc + qt * 128) * 8;
            const uint4* ql = (const uint4*)g_Qlo + ((long long)bh * Sc + qt * 128) * 8;
            #pragma unroll
            for (int i = tid; i < 128 * 8; i += 256) {
                int r = i >> 3, w = i & 7;
                int off = STAGE + r * KROW + w * 16;
                *(uint4*)(smem + OFF_KHI + off) = qh[i];
                *(uint4*)(smem + OFF_KLO + off) = ql[i];
            }
        }
        __syncthreads();
        uint32_t qfh[4][2][4], qfl[4][2][4];
        #pragma unroll
        for (int kk = 0; kk < 4; ++kk)
            #pragma unroll
            for (int m = 0; m < 2; ++m) {
                int base = STAGE + (r0a + m * 16) * KROW + (kk * 16 + 2 * tig) * 2;
                qfh[kk][m][0] = *(const uint32_t*)(smem + OFF_KHI + base);
                qfh[kk][m][1] = *(const uint32_t*)(smem + OFF_KHI + base + 8 * KROW);
                qfh[kk][m][2] = *(const uint32_t*)(smem + OFF_KHI + base + 16);
                qfh[kk][m][3] = *(const uint32_t*)(smem + OFF_KHI + base + 8 * KROW + 16);
                qfl[kk][m][0] = *(const uint32_t*)(smem + OFF_KLO + base);
                qfl[kk][m][1] = *(const uint32_t*)(smem + OFF_KLO + base + 8 * KROW);
                qfl[kk][m][2] = *(const uint32_t*)(smem + OFF_KLO + base + 16);
                qfl[kk][m][3] = *(const uint32_t*)(smem + OFF_KLO + base + 8 * KROW + 16);
            }
        __syncthreads();   // done reading Q before stage 1 is refilled

        const unsigned* mr0 = g_maskbits + (long long)(qt * 128 + r0a) * 64;
        const unsigned* mr1 = mr0 + 8 * 64;
        const unsigned* mr2 = mr0 + 16 * 64;
        const unsigned* mr3 = mr0 + 24 * 64;
        float ls0 = 0.f, ls1 = 0.f, ls2 = 0.f, ls3 = 0.f;
        float* const ab = attn + ((long long)bh * Sc + qt * 128 + r0a) * Sc;

        for (int kt = 0; kt < NKT; ++kt) {
            CP_WAIT(0);
            __syncthreads();                        // tile kt ready; other buf free
            if (kt + 1 < NKT) {
                preload_k(smb + ((kt + 1) & 1) * STAGE, bh, kt + 1, tid);
                CP_COMMIT();
            }
            const uint32_t bufK = smb + (kt & 1) * STAGE;
            const int wi = kt * 4 + ng * 2;
            unsigned mwa[2] = { mr0[wi], mr0[wi + 1] };
            unsigned mwb[2] = { mr1[wi], mr1[wi + 1] };
            unsigned mwc[2] = { mr2[wi], mr2[wi + 1] };
            unsigned mwd[2] = { mr3[wi], mr3[wi + 1] };
            float* arow = ab + kt * 128 + ncol0;

            #pragma unroll
            for (int nb = 0; nb < 8; ++nb) {
                uint32_t bH[8], bL[8];
                uint32_t rowoff = (uint32_t)((ncol0 + nb * 8) * KROW) + ldK_base;
                ldsm_x4(bH[0], bH[1], bH[2], bH[3], bufK + OFF_KHI + rowoff);
                ldsm_x4(bH[4], bH[5], bH[6], bH[7], bufK + OFF_KHI + rowoff + 64);
                ldsm_x4(bL[0], bL[1], bL[2], bL[3], bufK + OFF_KLO + rowoff);
                ldsm_x4(bL[4], bL[5], bL[6], bL[7], bufK + OFF_KLO + rowoff + 64);
                float cA1[4] = {0.f,0.f,0.f,0.f}, cA2[4] = {0.f,0.f,0.f,0.f};
                float cB1[4] = {0.f,0.f,0.f,0.f}, cB2[4] = {0.f,0.f,0.f,0.f};
                #pragma unroll
                for (int kk = 0; kk < 4; ++kk) {
                    uint32_t b0 = bH[2 * kk], b1 = bH[2 * kk + 1];
                    uint32_t l0 = bL[2 * kk], l1 = bL[2 * kk + 1];
                    mma16816(cA1, qfh[kk][0], b0, b1);
                    mma16816(cB1, qfh[kk][1], b0, b1);
                    mma16816(cA2, qfh[kk][0], l0, l1);
                    mma16816(cA2, qfl[kk][0], b0, b1);
                    mma16816(cB2, qfh[kk][1], l0, l1);
                    mma16816(cB2, qfl[kk][1], b0, b1);
                }
                int bit = (nb & 3) * 8 + 2 * tig;
                unsigned wa = mwa[nb >> 2], wb = mwb[nb >> 2];
                unsigned wc = mwc[nb >> 2], wd = mwd[nb >> 2];
                float pa0 = ((wa >> bit) & 1u)       ? __expf(cA1[0] + cA2[0]) : 0.f;
                float pa1 = ((wa >> (bit + 1)) & 1u) ? __expf(cA1[1] + cA2[1]) : 0.f;
                float pb0 = ((wb >> bit) & 1u)       ? __expf(cA1[2] + cA2[2]) : 0.f;
                float pb1 = ((wb >> (bit + 1)) & 1u) ? __expf(cA1[3] + cA2[3]) : 0.f;
                float pc0 = ((wc >> bit) & 1u)       ? __expf(cB1[0] + cB2[0]) : 0.f;
                float pc1 = ((wc >> (bit + 1)) & 1u) ? __expf(cB1[1] + cB2[1]) : 0.f;
                float pd0 = ((wd >> bit) & 1u)       ? __expf(cB1[2] + cB2[2]) : 0.f;
                float pd1 = ((wd >> (bit + 1)) & 1u) ? __expf(cB1[3] + cB2[3]) : 0.f;
                ls0 += pa0 + pa1;  ls1 += pb0 + pb1;
                ls2 += pc0 + pc1;  ls3 += pd0 + pd1;
                int cc = nb * 8 + 2 * tig;
                *(float2*)(arow + cc)           = make_float2(pa0, pa1);
                *(float2*)(arow + 8 * Sc + cc)  = make_float2(pb0, pb1);
                *(float2*)(arow + 16 * Sc + cc) = make_float2(pc0, pc1);
                *(float2*)(arow + 24 * Sc + cc) = make_float2(pd0, pd1);
            }
        }

        // overlap first V prefetch (for reversed phase 2: kt=15) with reduction.
        // stage 0 is safe: the kt=15 barrier guaranteed everyone is done with it.
        preload_v(smb + 0 * STAGE, bh, NKT - 1, tid);
        CP_COMMIT();

        // quad-reduce and publish partial sums
        ls0 += __shfl_xor_sync(0xffffffffu, ls0, 1);
        ls0 += __shfl_xor_sync(0xffffffffu, ls0, 2);
        ls1 += __shfl_xor_sync(0xffffffffu, ls1, 1);
        ls1 += __shfl_xor_sync(0xffffffffu, ls1, 2);
        ls2 += __shfl_xor_sync(0xffffffffu, ls2, 1);
        ls2 += __shfl_xor_sync(0xffffffffu, ls2, 2);
        ls3 += __shfl_xor_sync(0xffffffffu, ls3, 1);
        ls3 += __shfl_xor_sync(0xffffffffu, ls3, 2);
        float* lsArr = (float*)(smem + OFF_LS);
        if (tig == 0) {
            lsArr[ng * 128 + r0a]      = ls0;
            lsArr[ng * 128 + r0a + 8]  = ls1;
            lsArr[ng * 128 + r0a + 16] = ls2;
            lsArr[ng * 128 + r0a + 24] = ls3;
        }
        __syncthreads();
        if (tid < 128) {
            float l = lsArr[tid] + lsArr[128 + tid];
            ((float*)(smem + OFF_RV))[tid] = (l > 0.f) ? 1.f / l : 0.f;
        }
        __syncthreads();
    }

    // ================ PHASE 2 (kt reversed 15->0): read e, normalize, PV ====
    const int r0 = wid * 16 + gid;
    const long long qrow0 = (long long)qt * 128 + r0;
    const float rinv0 = ((const float*)(smem + OFF_RV))[r0];
    const float rinv1 = ((const float*)(smem + OFF_RV))[r0 + 8];
    float* const abase = attn + ((long long)bh * Sc + qrow0) * Sc;

    float o[8][4];
    #pragma unroll
    for (int nd = 0; nd < 8; ++nd)
        #pragma unroll
        for (int j = 0; j < 4; ++j) o[nd][j] = 0.f;

    // initial e-fragment load for (kt=15, kc=0) — written most recently, L2-hot
    float2 f0, f1, f2, f3;
    {
        float* arow0 = abase + (NKT - 1) * 128;
        int cc = 2 * tig;
        f0 = *(float2*)(arow0 + cc);
        f1 = *(float2*)(arow0 + 8 * Sc + cc);
        f2 = *(float2*)(arow0 + 8 + cc);
        f3 = *(float2*)(arow0 + 8 * Sc + 8 + cc);
    }

    for (int kt = NKT - 1; kt >= 0; --kt) {
        CP_WAIT(0);
        __syncthreads();
        if (kt > 0) {
            preload_v(smb + (kt & 1) * STAGE, bh, kt - 1, tid);
            CP_COMMIT();
        }
        const uint32_t bufV = smb + ((kt + 1) & 1) * STAGE;
        float* arow0 = abase + kt * 128;
        float* arowN = abase + (kt - 1) * 128;   // next tile (only used when kt>0)

        #pragma unroll
        for (int kc = 0; kc < 8; ++kc) {
            float2 g0, g1, g2, g3;
            if (kc < 7) {
                int cc = (kc + 1) * 16 + 2 * tig;
                g0 = *(float2*)(arow0 + cc);
                g1 = *(float2*)(arow0 + 8 * Sc + cc);
                g2 = *(float2*)(arow0 + 8 + cc);
                g3 = *(float2*)(arow0 + 8 * Sc + 8 + cc);
            } else if (kt > 0) {
                // cross-kt prefetch: first e-fragments of the next tile
                int cc = 2 * tig;
                g0 = *(float2*)(arowN + cc);
                g1 = *(float2*)(arowN + 8 * Sc + cc);
                g2 = *(float2*)(arowN + 8 + cc);
                g3 = *(float2*)(arowN + 8 * Sc + 8 + cc);
            }
            float p0 = f0.x * rinv0, p1 = f0.y * rinv0;
            float p2 = f1.x * rinv1, p3 = f1.y * rinv1;
            float p4 = f2.x * rinv0, p5 = f2.y * rinv0;
            float p6 = f3.x * rinv1, p7 = f3.y * rinv1;
            {
                int cc = kc * 16 + 2 * tig;
                *(float2*)(arow0 + cc)              = make_float2(p0, p1);
                *(float2*)(arow0 + 8 * Sc + cc)     = make_float2(p2, p3);
                *(float2*)(arow0 + 8 + cc)          = make_float2(p4, p5);
                *(float2*)(arow0 + 8 * Sc + 8 + cc) = make_float2(p6, p7);
            }
            uint32_t aH[4], aL[4];
            float h0 = __bfloat162float(__float2bfloat16(p0));
            float h1 = __bfloat162float(__float2bfloat16(p1));
            float h2 = __bfloat162float(__float2bfloat16(p2));
            float h3 = __bfloat162float(__float2bfloat16(p3));
            aH[0] = pk2(h0, h1); aH[1] = pk2(h2, h3);
            aL[0] = pk2(p0 - h0, p1 - h1); aL[1] = pk2(p2 - h2, p3 - h3);
            h0 = __bfloat162float(__float2bfloat16(p4));
            h1 = __bfloat162float(__float2bfloat16(p5));
            h2 = __bfloat162float(__float2bfloat16(p6));
            h3 = __bfloat162float(__float2bfloat16(p7));
            aH[2] = pk2(h0, h1); aH[3] = pk2(h2, h3);
            aL[2] = pk2(p4 - h0, p5 - h1); aL[3] = pk2(p6 - h2, p7 - h3);

            #pragma unroll
            for (int p = 0; p < 4; ++p) {
                uint32_t addr = bufV + (uint32_t)(p * 16 * VROW + kc * 32) + ldV_base;
                uint32_t vh0, vh1, vh2, vh3, vl0, vl1, vl2, vl3;
                ldsm_x4(vh0, vh1, vh2, vh3, addr + OFF_VHI);
                ldsm_x4(vl0, vl1, vl2, vl3, addr + OFF_VLO);
                mma16816(o[2 * p],     aH, vh0, vh1);
                mma16816(o[2 * p],     aH, vl0, vl1);
                mma16816(o[2 * p],     aL, vh0, vh1);
                mma16816(o[2 * p + 1], aH, vh2, vh3);
                mma16816(o[2 * p + 1], aH, vl2, vl3);
                mma16816(o[2 * p + 1], aL, vh2, vh3);
            }
            f0 = g0; f1 = g1; f2 = g2; f3 = g3;
        }
    }

    // ---- write O ----
    {
        float* orow = out + ((long long)bh * Sc + qrow0) * Dc;
        #pragma unroll
        for (int nd = 0; nd < 8; ++nd) {
            int cc = nd * 8 + 2 * tig;
            *(float2*)(orow + cc)          = make_float2(o[nd][0], o[nd][1]);
            *(float2*)(orow + 8 * Dc + cc) = make_float2(o[nd][2], o[nd][3]);
        }
    }
}

// ---------------- launcher ----------------
extern "C" void kernel_launch(void* const* d_in, const int* in_sizes, int n_in,
                              void* d_out, int out_size) {
    const float* q = (const float*)d_in[0];
    const float* k = (const float*)d_in[1];
    const float* v = (const float*)d_in[2];
    const int*   m = (const int*)d_in[3];
    float* out  = (float*)d_out;
    float* attn = out + OUT_ELEMS;

    cudaFuncSetAttribute(attn_main_kernel,
                         cudaFuncAttributeMaxDynamicSharedMemorySize, SMEM_BYTES);

    conv_qk_kernel<<<QKD / 256, 256>>>(q, k);
    conv_v_kernel<<<BHc * (Sc / 64), 256>>>(v);
    pack_mask_kernel<<<MASKW / 256, 256>>>(m);
    attn_main_kernel<<<dim3(NKT, BHc), 256, SMEM_BYTES>>>(out, attn);
}